// round 1
// baseline (speedup 1.0000x reference)
#include <cuda_runtime.h>
#include <math.h>

#define DIM  2048
#define NH   16
#define NKV  4
#define HD   128
#define GRP  (NH / NKV)
#define TSEQ 2048
#define BMAX 2

// ---------------- scratch (device globals; no allocation allowed) ----------
__device__ float g_wq[DIM * DIM];
__device__ float g_wk[NKV * HD * DIM];
__device__ float g_wv[NKV * HD * DIM];
__device__ float g_wp[DIM * DIM];
__device__ float g_q[BMAX * TSEQ * DIM];
__device__ float g_k[BMAX * TSEQ * NKV * HD];
__device__ float g_v[BMAX * TSEQ * NKV * HD];
__device__ float g_y[BMAX * TSEQ * DIM];

// ---------------- weight quantization: W_eff = w + sf*(w_quant - w) --------
__global__ void prep_w(const float* __restrict__ w, float* __restrict__ o,
                       const float* __restrict__ sfp) {
    const int row = blockIdx.x;
    const float* wr = w + (size_t)row * DIM;
    float* orow = o + (size_t)row * DIM;

    float part = 0.0f;
    for (int c = threadIdx.x; c < DIM; c += blockDim.x) part += fabsf(wr[c]);

    __shared__ float sh[8];
    #pragma unroll
    for (int off = 16; off; off >>= 1)
        part += __shfl_xor_sync(0xffffffffu, part, off);
    if ((threadIdx.x & 31) == 0) sh[threadIdx.x >> 5] = part;
    __syncthreads();
    float tot = 0.0f;
    #pragma unroll
    for (int i = 0; i < 8; i++) tot += sh[i];

    const float scale = fmaxf(tot * (1.0f / (float)DIM), 1e-8f);
    const float thr = 0.7f * scale;
    const float sf = *sfp;
    for (int c = threadIdx.x; c < DIM; c += blockDim.x) {
        float wv = wr[c];
        float wq = (fabsf(wv) > thr) ? copysignf(scale, wv) : 0.0f;
        orow[c] = wv + sf * (wq - wv);
    }
}

// ---------------- fp32 NT GEMM: C[M,N] = A[M,K] * B[N,K]^T ------------------
// BM=BN=128, BK=8, 256 threads, 8x8 microtile per thread.
__global__ __launch_bounds__(256)
void gemm_nt(const float* __restrict__ A, const float* __restrict__ Bm,
             float* __restrict__ C, int M, int N, int K) {
    __shared__ float As[8][132];
    __shared__ float Bs[8][132];

    const int tid = threadIdx.x;
    const int tx = tid & 15;      // N quad
    const int ty = tid >> 4;      // M quad
    const int m0 = blockIdx.y * 128;
    const int n0 = blockIdx.x * 128;

    const int lm = tid >> 1;             // 0..127
    const int lk = (tid & 1) * 4;        // 0 or 4
    const float* Ap = A + (size_t)(m0 + lm) * K + lk;
    const float* Bp = Bm + (size_t)(n0 + lm) * K + lk;

    float acc[8][8];
    #pragma unroll
    for (int i = 0; i < 8; i++)
        #pragma unroll
        for (int j = 0; j < 8; j++) acc[i][j] = 0.0f;

    for (int k0 = 0; k0 < K; k0 += 8) {
        float4 a4 = *(const float4*)(Ap + k0);
        float4 b4 = *(const float4*)(Bp + k0);
        As[lk + 0][lm] = a4.x; As[lk + 1][lm] = a4.y;
        As[lk + 2][lm] = a4.z; As[lk + 3][lm] = a4.w;
        Bs[lk + 0][lm] = b4.x; Bs[lk + 1][lm] = b4.y;
        Bs[lk + 2][lm] = b4.z; Bs[lk + 3][lm] = b4.w;
        __syncthreads();

        #pragma unroll
        for (int kk = 0; kk < 8; kk++) {
            float ra[8], rb[8];
            #pragma unroll
            for (int i = 0; i < 8; i++) ra[i] = As[kk][ty * 8 + i];
            #pragma unroll
            for (int j = 0; j < 8; j++) rb[j] = Bs[kk][tx + 16 * j];
            #pragma unroll
            for (int i = 0; i < 8; i++)
                #pragma unroll
                for (int j = 0; j < 8; j++)
                    acc[i][j] = fmaf(ra[i], rb[j], acc[i][j]);
        }
        __syncthreads();
    }

    #pragma unroll
    for (int i = 0; i < 8; i++) {
        const size_t row = (size_t)(m0 + ty * 8 + i);
        #pragma unroll
        for (int j = 0; j < 8; j++)
            C[row * N + n0 + tx + 16 * j] = acc[i][j];
    }
}

// ---------------- fused RMSNorm + RoPE (+ q_gain) ---------------------------
__global__ void rms_rope(float* __restrict__ data, const float* __restrict__ gain,
                         int heads, int isq) {
    const int bt = blockIdx.x;
    const int hh = blockIdx.y;
    const int d = threadIdx.x;  // 128 threads
    float* ptr = data + ((size_t)bt * heads + hh) * HD;

    float v = ptr[d];
    float ss = v * v;
    __shared__ float sh[4];
    #pragma unroll
    for (int off = 16; off; off >>= 1)
        ss += __shfl_xor_sync(0xffffffffu, ss, off);
    if ((d & 31) == 0) sh[d >> 5] = ss;
    __syncthreads();
    float tot = sh[0] + sh[1] + sh[2] + sh[3];
    float rs = rsqrtf(tot * (1.0f / (float)HD) + 1.1920928955078125e-07f);

    __shared__ float sn[HD];
    sn[d] = v * rs;
    __syncthreads();

    if (d < HD / 2) {
        const int t = bt % TSEQ;
        float invf = 1.0f / powf(10000.0f, (float)d * (2.0f / (float)HD));
        float ang = (float)t * invf;
        float c = cosf(ang), s = sinf(ang);
        float x1 = sn[d], x2 = sn[d + HD / 2];
        float g = isq ? gain[hh] : 1.0f;
        ptr[d] = (x1 * c + x2 * s) * g;
        ptr[d + HD / 2] = (x2 * c - x1 * s) * g;
    }
}

// ---------------- causal flash attention (fp32 SIMT) ------------------------
// 64 query rows per block, one (b,h) per blockIdx.y. 256 threads.
__global__ __launch_bounds__(256)
void attn(const float* __restrict__ q, const float* __restrict__ k,
          const float* __restrict__ v, float* __restrict__ y, int T) {
    extern __shared__ float sm[];
    float* Qs = sm;                 // [64][129]
    float* Ks = Qs + 64 * 129;      // [64][129]
    float* Vs = Ks + 64 * 129;      // [64][129]
    float* Ps = Vs + 64 * 129;      // [64][65]

    const int qb = (gridDim.x - 1) - blockIdx.x;   // heavy blocks first
    const int bh = blockIdx.y;
    const int b = bh / NH, h = bh % NH, kv = h / GRP;
    const int tid = threadIdx.x;
    const int tx = tid & 15, ty = tid >> 4;

    for (int idx = tid; idx < 64 * HD; idx += 256) {
        int r = idx >> 7, d = idx & 127;
        Qs[r * 129 + d] = q[((size_t)(b * T + qb * 64 + r) * NH + h) * HD + d];
    }

    float m_i[4], l_i[4], O[4][8];
    #pragma unroll
    for (int i = 0; i < 4; i++) {
        m_i[i] = -1e30f; l_i[i] = 0.0f;
        #pragma unroll
        for (int c = 0; c < 8; c++) O[i][c] = 0.0f;
    }
    const float sc = 0.08838834764831845f;  // 1/sqrt(128)

    for (int kb = 0; kb <= qb; kb++) {
        __syncthreads();  // previous PV done before overwriting K/V
        for (int idx = tid; idx < 64 * HD; idx += 256) {
            int r = idx >> 7, d = idx & 127;
            size_t base = ((size_t)(b * T + kb * 64 + r) * NKV + kv) * HD + d;
            Ks[r * 129 + d] = k[base];
            Vs[r * 129 + d] = v[base];
        }
        __syncthreads();

        float s_acc[4][4];
        #pragma unroll
        for (int i = 0; i < 4; i++)
            #pragma unroll
            for (int j = 0; j < 4; j++) s_acc[i][j] = 0.0f;

        #pragma unroll 4
        for (int d = 0; d < HD; d++) {
            float ra[4], rb[4];
            #pragma unroll
            for (int i = 0; i < 4; i++) ra[i] = Qs[(ty * 4 + i) * 129 + d];
            #pragma unroll
            for (int j = 0; j < 4; j++) rb[j] = Ks[(tx * 4 + j) * 129 + d];
            #pragma unroll
            for (int i = 0; i < 4; i++)
                #pragma unroll
                for (int j = 0; j < 4; j++)
                    s_acc[i][j] = fmaf(ra[i], rb[j], s_acc[i][j]);
        }

        #pragma unroll
        for (int i = 0; i < 4; i++) {
            const int trow = qb * 64 + ty * 4 + i;
            float pv[4];
            float rm = -1e30f;
            #pragma unroll
            for (int j = 0; j < 4; j++) {
                int scol = kb * 64 + tx * 4 + j;
                float sv = (scol <= trow) ? s_acc[i][j] * sc : -1e30f;
                pv[j] = sv;
                rm = fmaxf(rm, sv);
            }
            #pragma unroll
            for (int off = 8; off; off >>= 1)
                rm = fmaxf(rm, __shfl_xor_sync(0xffffffffu, rm, off));
            float mnew = fmaxf(m_i[i], rm);
            float alpha = expf(m_i[i] - mnew);
            float psum = 0.0f;
            #pragma unroll
            for (int j = 0; j < 4; j++) {
                pv[j] = expf(pv[j] - mnew);
                psum += pv[j];
                Ps[(ty * 4 + i) * 65 + tx * 4 + j] = pv[j];
            }
            #pragma unroll
            for (int off = 8; off; off >>= 1)
                psum += __shfl_xor_sync(0xffffffffu, psum, off);
            l_i[i] = l_i[i] * alpha + psum;
            m_i[i] = mnew;
            #pragma unroll
            for (int c = 0; c < 8; c++) O[i][c] *= alpha;
        }
        __syncthreads();  // P visible to all before PV

        #pragma unroll 2
        for (int s = 0; s < 64; s++) {
            float rp[4], rv[8];
            #pragma unroll
            for (int i = 0; i < 4; i++) rp[i] = Ps[(ty * 4 + i) * 65 + s];
            #pragma unroll
            for (int c = 0; c < 8; c++) rv[c] = Vs[s * 129 + tx + 16 * c];
            #pragma unroll
            for (int i = 0; i < 4; i++)
                #pragma unroll
                for (int c = 0; c < 8; c++)
                    O[i][c] = fmaf(rp[i], rv[c], O[i][c]);
        }
    }

    #pragma unroll
    for (int i = 0; i < 4; i++) {
        float inv = 1.0f / l_i[i];
        size_t base = ((size_t)(b * T + qb * 64 + ty * 4 + i) * NH + h) * HD;
        #pragma unroll
        for (int c = 0; c < 8; c++)
            y[base + tx + 16 * c] = O[i][c] * inv;
    }
}

// ---------------- v-orthogonalization: y -= (y.vn) vn -----------------------
__device__ __forceinline__ float blk_sum_128(float val, float* sh) {
    #pragma unroll
    for (int off = 16; off; off >>= 1)
        val += __shfl_xor_sync(0xffffffffu, val, off);
    if ((threadIdx.x & 31) == 0) sh[threadIdx.x >> 5] = val;
    __syncthreads();
    float tot = sh[0] + sh[1] + sh[2] + sh[3];
    __syncthreads();
    return tot;
}

__global__ void vorth(const float* __restrict__ v, float* __restrict__ y) {
    __shared__ float sh[4];
    const int bt = blockIdx.x / NKV;
    const int kvh = blockIdx.x % NKV;
    const int d = threadIdx.x;  // 128

    float vv = v[((size_t)bt * NKV + kvh) * HD + d];
    float ss = blk_sum_128(vv * vv, sh);
    float nrm = sqrtf(ss);
    float vn = vv / fmaxf(nrm, 1e-12f);

    for (int g = 0; g < GRP; g++) {
        float* yp = y + ((size_t)bt * NH + kvh * GRP + g) * HD;
        float yv = yp[d];
        float dot = blk_sum_128(yv * vn, sh);
        yp[d] = yv - dot * vn;
    }
}

// ---------------- launcher ---------------------------------------------------
extern "C" void kernel_launch(void* const* d_in, const int* in_sizes, int n_in,
                              void* d_out, int out_size) {
    const float* x    = (const float*)d_in[0];
    const float* sfp  = (const float*)d_in[1];
    const float* wq   = (const float*)d_in[2];
    const float* wk   = (const float*)d_in[3];
    const float* wv   = (const float*)d_in[4];
    const float* wp   = (const float*)d_in[5];
    const float* gain = (const float*)d_in[6];

    const int BT = in_sizes[0] / DIM;   // B*T = 4096
    const int T = TSEQ;
    const int Bb = BT / T;

    float *pwq, *pwk, *pwv, *pwp, *pq, *pk, *pv, *py;
    cudaGetSymbolAddress((void**)&pwq, g_wq);
    cudaGetSymbolAddress((void**)&pwk, g_wk);
    cudaGetSymbolAddress((void**)&pwv, g_wv);
    cudaGetSymbolAddress((void**)&pwp, g_wp);
    cudaGetSymbolAddress((void**)&pq, g_q);
    cudaGetSymbolAddress((void**)&pk, g_k);
    cudaGetSymbolAddress((void**)&pv, g_v);
    cudaGetSymbolAddress((void**)&py, g_y);

    // 1) effective weights
    prep_w<<<DIM, 256>>>(wq, pwq, sfp);
    prep_w<<<NKV * HD, 256>>>(wk, pwk, sfp);
    prep_w<<<NKV * HD, 256>>>(wv, pwv, sfp);
    prep_w<<<DIM, 256>>>(wp, pwp, sfp);

    // 2) QKV projections
    gemm_nt<<<dim3(DIM / 128, BT / 128), 256>>>(x, pwq, pq, BT, DIM, DIM);
    gemm_nt<<<dim3(NKV * HD / 128, BT / 128), 256>>>(x, pwk, pk, BT, NKV * HD, DIM);
    gemm_nt<<<dim3(NKV * HD / 128, BT / 128), 256>>>(x, pwv, pv, BT, NKV * HD, DIM);

    // 3) RMS norm + RoPE (+gain on q)
    rms_rope<<<dim3(BT, NH), 128>>>(pq, gain, NH, 1);
    rms_rope<<<dim3(BT, NKV), 128>>>(pk, gain, NKV, 0);

    // 4) causal flash attention
    size_t smem = (size_t)(3 * 64 * 129 + 64 * 65) * sizeof(float);
    cudaFuncSetAttribute(attn, cudaFuncAttributeMaxDynamicSharedMemorySize, (int)smem);
    attn<<<dim3(T / 64, Bb * NH), 256, smem>>>(pq, pk, pv, py, T);

    // 5) v-orthogonalization (in place on y)
    vorth<<<BT * NKV, 128>>>(pv, py);

    // 6) output projection -> d_out
    gemm_nt<<<dim3(DIM / 128, BT / 128), 256>>>(py, pwp, (float*)d_out, BT, DIM, DIM);
}

// round 3
// speedup vs baseline: 1.5798x; 1.5798x over previous
#include <cuda_runtime.h>
#include <cuda_bf16.h>
#include <cstdint>
#include <math.h>

#define DIM  2048
#define NH   16
#define NKV  4
#define HD   128
#define GRP  (NH / NKV)
#define TSEQ 2048
#define BMAX 2

// ---------------- scratch (device globals; no allocation allowed) ----------
__device__ __nv_bfloat16 g_wq_h[DIM * DIM];
__device__ __nv_bfloat16 g_wq_l[DIM * DIM];
__device__ __nv_bfloat16 g_wk_h[NKV * HD * DIM];
__device__ __nv_bfloat16 g_wk_l[NKV * HD * DIM];
__device__ __nv_bfloat16 g_wv_h[NKV * HD * DIM];
__device__ __nv_bfloat16 g_wv_l[NKV * HD * DIM];
__device__ __nv_bfloat16 g_wp_h[DIM * DIM];
__device__ __nv_bfloat16 g_wp_l[DIM * DIM];
__device__ __nv_bfloat16 g_a_h[BMAX * TSEQ * DIM];   // activation split (x, then y)
__device__ __nv_bfloat16 g_a_l[BMAX * TSEQ * DIM];
__device__ float g_q[BMAX * TSEQ * DIM];
__device__ float g_k[BMAX * TSEQ * NKV * HD];
__device__ float g_v[BMAX * TSEQ * NKV * HD];
__device__ float g_y[BMAX * TSEQ * DIM];

__device__ __forceinline__ void split_bf16(float v, __nv_bfloat16& h, __nv_bfloat16& l) {
    h = __float2bfloat16_rn(v);
    l = __float2bfloat16_rn(v - __bfloat162float(h));
}

// ---------------- weight quantization + bf16 split --------------------------
__global__ void prep_w(const float* __restrict__ w,
                       __nv_bfloat16* __restrict__ oh, __nv_bfloat16* __restrict__ ol,
                       const float* __restrict__ sfp) {
    const int row = blockIdx.x;
    const float* wr = w + (size_t)row * DIM;

    float part = 0.0f;
    for (int c = threadIdx.x; c < DIM; c += blockDim.x) part += fabsf(wr[c]);

    __shared__ float sh[8];
    #pragma unroll
    for (int off = 16; off; off >>= 1)
        part += __shfl_xor_sync(0xffffffffu, part, off);
    if ((threadIdx.x & 31) == 0) sh[threadIdx.x >> 5] = part;
    __syncthreads();
    float tot = 0.0f;
    #pragma unroll
    for (int i = 0; i < 8; i++) tot += sh[i];

    const float scale = fmaxf(tot * (1.0f / (float)DIM), 1e-8f);
    const float thr = 0.7f * scale;
    const float sf = *sfp;
    for (int c = threadIdx.x; c < DIM; c += blockDim.x) {
        float wv = wr[c];
        float wqv = (fabsf(wv) > thr) ? copysignf(scale, wv) : 0.0f;
        float eff = wv + sf * (wqv - wv);
        __nv_bfloat16 h, l;
        split_bf16(eff, h, l);
        oh[(size_t)row * DIM + c] = h;
        ol[(size_t)row * DIM + c] = l;
    }
}

// ---------------- fp32 -> bf16 hi/lo split for activations ------------------
__global__ void split_act(const float* __restrict__ in,
                          __nv_bfloat16* __restrict__ hi, __nv_bfloat16* __restrict__ lo,
                          int n4) {
    int i = blockIdx.x * blockDim.x + threadIdx.x;
    if (i >= n4) return;
    float4 v = ((const float4*)in)[i];
    __nv_bfloat16 h[4], l[4];
    split_bf16(v.x, h[0], l[0]);
    split_bf16(v.y, h[1], l[1]);
    split_bf16(v.z, h[2], l[2]);
    split_bf16(v.w, h[3], l[3]);
    ((uint2*)hi)[i] = *(uint2*)h;
    ((uint2*)lo)[i] = *(uint2*)l;
}

// ---------------- bf16-split tensor-core NT GEMM ----------------------------
// C[M,N] = A[M,K]*B[N,K]^T with A,B given as bf16 (hi,lo) pairs.
// C = Ah*Bh + Ah*Bl + Al*Bh  (fp32 accumulate)  ~ fp32 precision.
// BM=BN=128, BK=32, 256 threads = 8 warps (2x4), warp tile 64x32,
// per warp 4x4 mma.m16n8k16 tiles.
#define LDS_K 40   // 32 + 8 halfs padding

__device__ __forceinline__ uint32_t lds_u32(const __nv_bfloat16* p) {
    return *(const uint32_t*)p;
}

__device__ __forceinline__ void mma_bf16(float d[4], const uint32_t a[4],
                                         const uint32_t b[2]) {
    asm volatile(
        "mma.sync.aligned.m16n8k16.row.col.f32.bf16.bf16.f32 "
        "{%0,%1,%2,%3}, {%4,%5,%6,%7}, {%8,%9}, {%0,%1,%2,%3};\n"
        : "+f"(d[0]), "+f"(d[1]), "+f"(d[2]), "+f"(d[3])
        : "r"(a[0]), "r"(a[1]), "r"(a[2]), "r"(a[3]), "r"(b[0]), "r"(b[1]));
}

__global__ __launch_bounds__(256)
void gemm_nt_split(const __nv_bfloat16* __restrict__ Ah, const __nv_bfloat16* __restrict__ Al,
                   const __nv_bfloat16* __restrict__ Bh, const __nv_bfloat16* __restrict__ Bl,
                   float* __restrict__ C, int M, int N, int K) {
    __shared__ __nv_bfloat16 sAh[128 * LDS_K];
    __shared__ __nv_bfloat16 sAl[128 * LDS_K];
    __shared__ __nv_bfloat16 sBh[128 * LDS_K];
    __shared__ __nv_bfloat16 sBl[128 * LDS_K];

    const int tid = threadIdx.x;
    const int lane = tid & 31;
    const int g = lane >> 2;        // 0..7
    const int tig = lane & 3;       // 0..3
    const int wm = (tid >> 5) & 1;  // warp M (0..1)
    const int wn = tid >> 6;        // warp N (0..3)
    const int m0 = blockIdx.y * 128;
    const int n0 = blockIdx.x * 128;

    float acc[4][4][4];
    #pragma unroll
    for (int i = 0; i < 4; i++)
        #pragma unroll
        for (int j = 0; j < 4; j++)
            #pragma unroll
            for (int r = 0; r < 4; r++) acc[i][j][r] = 0.0f;

    // smem fragment base offsets (in halfs)
    const int a_base = (wm * 64 + g) * LDS_K + tig * 2;
    const int b_base = (wn * 32 + g) * LDS_K + tig * 2;

    for (int k0 = 0; k0 < K; k0 += 32) {
        // load 128x32 tiles of each array
        #pragma unroll
        for (int s = 0; s < 2; s++) {
            int chunk = tid + s * 256;       // 0..511
            int row = chunk >> 2;            // 0..127
            int part = chunk & 3;            // 0..3
            size_t goffA = (size_t)(m0 + row) * K + k0 + part * 8;
            size_t goffB = (size_t)(n0 + row) * K + k0 + part * 8;
            int soff = row * LDS_K + part * 8;
            *(uint4*)&sAh[soff] = *(const uint4*)&Ah[goffA];
            *(uint4*)&sAl[soff] = *(const uint4*)&Al[goffA];
            *(uint4*)&sBh[soff] = *(const uint4*)&Bh[goffB];
            *(uint4*)&sBl[soff] = *(const uint4*)&Bl[goffB];
        }
        __syncthreads();

        #pragma unroll
        for (int ks = 0; ks < 2; ks++) {
            const int koff = ks * 16;
            uint32_t af[4][4], bf_[4][2];

            // pass 1: Ah * Bh
            #pragma unroll
            for (int i = 0; i < 4; i++) {
                int base = a_base + i * 16 * LDS_K + koff;
                af[i][0] = lds_u32(&sAh[base]);
                af[i][1] = lds_u32(&sAh[base + 8 * LDS_K]);
                af[i][2] = lds_u32(&sAh[base + 8]);
                af[i][3] = lds_u32(&sAh[base + 8 * LDS_K + 8]);
            }
            #pragma unroll
            for (int j = 0; j < 4; j++) {
                int base = b_base + j * 8 * LDS_K + koff;
                bf_[j][0] = lds_u32(&sBh[base]);
                bf_[j][1] = lds_u32(&sBh[base + 8]);
            }
            #pragma unroll
            for (int i = 0; i < 4; i++)
                #pragma unroll
                for (int j = 0; j < 4; j++) mma_bf16(acc[i][j], af[i], bf_[j]);

            // pass 2: Ah * Bl
            #pragma unroll
            for (int j = 0; j < 4; j++) {
                int base = b_base + j * 8 * LDS_K + koff;
                bf_[j][0] = lds_u32(&sBl[base]);
                bf_[j][1] = lds_u32(&sBl[base + 8]);
            }
            #pragma unroll
            for (int i = 0; i < 4; i++)
                #pragma unroll
                for (int j = 0; j < 4; j++) mma_bf16(acc[i][j], af[i], bf_[j]);

            // pass 3: Al * Bh
            #pragma unroll
            for (int i = 0; i < 4; i++) {
                int base = a_base + i * 16 * LDS_K + koff;
                af[i][0] = lds_u32(&sAl[base]);
                af[i][1] = lds_u32(&sAl[base + 8 * LDS_K]);
                af[i][2] = lds_u32(&sAl[base + 8]);
                af[i][3] = lds_u32(&sAl[base + 8 * LDS_K + 8]);
            }
            #pragma unroll
            for (int j = 0; j < 4; j++) {
                int base = b_base + j * 8 * LDS_K + koff;
                bf_[j][0] = lds_u32(&sBh[base]);
                bf_[j][1] = lds_u32(&sBh[base + 8]);
            }
            #pragma unroll
            for (int i = 0; i < 4; i++)
                #pragma unroll
                for (int j = 0; j < 4; j++) mma_bf16(acc[i][j], af[i], bf_[j]);
        }
        __syncthreads();
    }

    // epilogue
    #pragma unroll
    for (int i = 0; i < 4; i++) {
        #pragma unroll
        for (int j = 0; j < 4; j++) {
            int row1 = m0 + wm * 64 + i * 16 + g;
            int col = n0 + wn * 32 + j * 8 + tig * 2;
            float2 lo = make_float2(acc[i][j][0], acc[i][j][1]);
            float2 hi = make_float2(acc[i][j][2], acc[i][j][3]);
            *(float2*)&C[(size_t)row1 * N + col] = lo;
            *(float2*)&C[(size_t)(row1 + 8) * N + col] = hi;
        }
    }
}

// ---------------- fused RMSNorm + RoPE (+ q_gain) ---------------------------
__global__ void rms_rope(float* __restrict__ data, const float* __restrict__ gain,
                         int heads, int isq) {
    const int bt = blockIdx.x;
    const int hh = blockIdx.y;
    const int d = threadIdx.x;  // 128 threads
    float* ptr = data + ((size_t)bt * heads + hh) * HD;

    float v = ptr[d];
    float ss = v * v;
    __shared__ float sh[4];
    #pragma unroll
    for (int off = 16; off; off >>= 1)
        ss += __shfl_xor_sync(0xffffffffu, ss, off);
    if ((d & 31) == 0) sh[d >> 5] = ss;
    __syncthreads();
    float tot = sh[0] + sh[1] + sh[2] + sh[3];
    float rs = rsqrtf(tot * (1.0f / (float)HD) + 1.1920928955078125e-07f);

    __shared__ float sn[HD];
    sn[d] = v * rs;
    __syncthreads();

    if (d < HD / 2) {
        const int t = bt % TSEQ;
        float invf = 1.0f / powf(10000.0f, (float)d * (2.0f / (float)HD));
        float ang = (float)t * invf;
        float c = cosf(ang), s = sinf(ang);
        float x1 = sn[d], x2 = sn[d + HD / 2];
        float gq = isq ? gain[hh] : 1.0f;
        ptr[d] = (x1 * c + x2 * s) * gq;
        ptr[d + HD / 2] = (x2 * c - x1 * s) * gq;
    }
}

// ---------------- causal flash attention (fp32 SIMT) ------------------------
__global__ __launch_bounds__(256)
void attn(const float* __restrict__ q, const float* __restrict__ k,
          const float* __restrict__ v, float* __restrict__ y, int T) {
    extern __shared__ float sm[];
    float* Qs = sm;                 // [64][129]
    float* Ks = Qs + 64 * 129;      // [64][129]
    float* Vs = Ks + 64 * 129;      // [64][129]
    float* Ps = Vs + 64 * 129;      // [64][65]

    const int qb = (gridDim.x - 1) - blockIdx.x;   // heavy blocks first
    const int bh = blockIdx.y;
    const int b = bh / NH, h = bh % NH, kv = h / GRP;
    const int tid = threadIdx.x;
    const int tx = tid & 15, ty = tid >> 4;

    for (int idx = tid; idx < 64 * HD; idx += 256) {
        int r = idx >> 7, d = idx & 127;
        Qs[r * 129 + d] = q[((size_t)(b * T + qb * 64 + r) * NH + h) * HD + d];
    }

    float m_i[4], l_i[4], O[4][8];
    #pragma unroll
    for (int i = 0; i < 4; i++) {
        m_i[i] = -1e30f; l_i[i] = 0.0f;
        #pragma unroll
        for (int c = 0; c < 8; c++) O[i][c] = 0.0f;
    }
    const float sc = 0.08838834764831845f;  // 1/sqrt(128)

    for (int kb = 0; kb <= qb; kb++) {
        __syncthreads();
        for (int idx = tid; idx < 64 * HD; idx += 256) {
            int r = idx >> 7, d = idx & 127;
            size_t base = ((size_t)(b * T + kb * 64 + r) * NKV + kv) * HD + d;
            Ks[r * 129 + d] = k[base];
            Vs[r * 129 + d] = v[base];
        }
        __syncthreads();

        float s_acc[4][4];
        #pragma unroll
        for (int i = 0; i < 4; i++)
            #pragma unroll
            for (int j = 0; j < 4; j++) s_acc[i][j] = 0.0f;

        #pragma unroll 4
        for (int d = 0; d < HD; d++) {
            float ra[4], rb[4];
            #pragma unroll
            for (int i = 0; i < 4; i++) ra[i] = Qs[(ty * 4 + i) * 129 + d];
            #pragma unroll
            for (int j = 0; j < 4; j++) rb[j] = Ks[(tx * 4 + j) * 129 + d];
            #pragma unroll
            for (int i = 0; i < 4; i++)
                #pragma unroll
                for (int j = 0; j < 4; j++)
                    s_acc[i][j] = fmaf(ra[i], rb[j], s_acc[i][j]);
        }

        #pragma unroll
        for (int i = 0; i < 4; i++) {
            const int trow = qb * 64 + ty * 4 + i;
            float pv[4];
            float rm = -1e30f;
            #pragma unroll
            for (int j = 0; j < 4; j++) {
                int scol = kb * 64 + tx * 4 + j;
                float sv = (scol <= trow) ? s_acc[i][j] * sc : -1e30f;
                pv[j] = sv;
                rm = fmaxf(rm, sv);
            }
            #pragma unroll
            for (int off = 8; off; off >>= 1)
                rm = fmaxf(rm, __shfl_xor_sync(0xffffffffu, rm, off));
            float mnew = fmaxf(m_i[i], rm);
            float alpha = expf(m_i[i] - mnew);
            float psum = 0.0f;
            #pragma unroll
            for (int j = 0; j < 4; j++) {
                pv[j] = expf(pv[j] - mnew);
                psum += pv[j];
                Ps[(ty * 4 + i) * 65 + tx * 4 + j] = pv[j];
            }
            #pragma unroll
            for (int off = 8; off; off >>= 1)
                psum += __shfl_xor_sync(0xffffffffu, psum, off);
            l_i[i] = l_i[i] * alpha + psum;
            m_i[i] = mnew;
            #pragma unroll
            for (int c = 0; c < 8; c++) O[i][c] *= alpha;
        }
        __syncthreads();

        #pragma unroll 2
        for (int s = 0; s < 64; s++) {
            float rp[4], rv[8];
            #pragma unroll
            for (int i = 0; i < 4; i++) rp[i] = Ps[(ty * 4 + i) * 65 + s];
            #pragma unroll
            for (int c = 0; c < 8; c++) rv[c] = Vs[s * 129 + tx + 16 * c];
            #pragma unroll
            for (int i = 0; i < 4; i++)
                #pragma unroll
                for (int c = 0; c < 8; c++)
                    O[i][c] = fmaf(rp[i], rv[c], O[i][c]);
        }
    }

    #pragma unroll
    for (int i = 0; i < 4; i++) {
        float inv = 1.0f / l_i[i];
        size_t base = ((size_t)(b * T + qb * 64 + ty * 4 + i) * NH + h) * HD;
        #pragma unroll
        for (int c = 0; c < 8; c++)
            y[base + tx + 16 * c] = O[i][c] * inv;
    }
}

// ---------------- v-orthogonalization: y -= (y.vn) vn -----------------------
__device__ __forceinline__ float blk_sum_128(float val, float* sh) {
    #pragma unroll
    for (int off = 16; off; off >>= 1)
        val += __shfl_xor_sync(0xffffffffu, val, off);
    if ((threadIdx.x & 31) == 0) sh[threadIdx.x >> 5] = val;
    __syncthreads();
    float tot = sh[0] + sh[1] + sh[2] + sh[3];
    __syncthreads();
    return tot;
}

__global__ void vorth(const float* __restrict__ v, float* __restrict__ y) {
    __shared__ float sh[4];
    const int bt = blockIdx.x / NKV;
    const int kvh = blockIdx.x % NKV;
    const int d = threadIdx.x;  // 128

    float vv = v[((size_t)bt * NKV + kvh) * HD + d];
    float ss = blk_sum_128(vv * vv, sh);
    float nrm = sqrtf(ss);
    float vn = vv / fmaxf(nrm, 1e-12f);

    for (int g = 0; g < GRP; g++) {
        float* yp = y + ((size_t)bt * NH + kvh * GRP + g) * HD;
        float yv = yp[d];
        float dot = blk_sum_128(yv * vn, sh);
        yp[d] = yv - dot * vn;
    }
}

// ---------------- launcher ---------------------------------------------------
extern "C" void kernel_launch(void* const* d_in, const int* in_sizes, int n_in,
                              void* d_out, int out_size) {
    const float* x    = (const float*)d_in[0];
    const float* sfp  = (const float*)d_in[1];
    const float* wq   = (const float*)d_in[2];
    const float* wk   = (const float*)d_in[3];
    const float* wv   = (const float*)d_in[4];
    const float* wp   = (const float*)d_in[5];
    const float* gain = (const float*)d_in[6];

    const int BT = in_sizes[0] / DIM;   // B*T = 4096
    const int T = TSEQ;
    const int Bb = BT / T;

    __nv_bfloat16 *pwqh, *pwql, *pwkh, *pwkl, *pwvh, *pwvl, *pwph, *pwpl, *pah, *pal;
    float *pq, *pk, *pv, *py;
    cudaGetSymbolAddress((void**)&pwqh, g_wq_h);
    cudaGetSymbolAddress((void**)&pwql, g_wq_l);
    cudaGetSymbolAddress((void**)&pwkh, g_wk_h);
    cudaGetSymbolAddress((void**)&pwkl, g_wk_l);
    cudaGetSymbolAddress((void**)&pwvh, g_wv_h);
    cudaGetSymbolAddress((void**)&pwvl, g_wv_l);
    cudaGetSymbolAddress((void**)&pwph, g_wp_h);
    cudaGetSymbolAddress((void**)&pwpl, g_wp_l);
    cudaGetSymbolAddress((void**)&pah, g_a_h);
    cudaGetSymbolAddress((void**)&pal, g_a_l);
    cudaGetSymbolAddress((void**)&pq, g_q);
    cudaGetSymbolAddress((void**)&pk, g_k);
    cudaGetSymbolAddress((void**)&pv, g_v);
    cudaGetSymbolAddress((void**)&py, g_y);

    // 1) effective weights -> bf16 hi/lo
    prep_w<<<DIM, 256>>>(wq, pwqh, pwql, sfp);
    prep_w<<<NKV * HD, 256>>>(wk, pwkh, pwkl, sfp);
    prep_w<<<NKV * HD, 256>>>(wv, pwvh, pwvl, sfp);
    prep_w<<<DIM, 256>>>(wp, pwph, pwpl, sfp);

    // 2) split x, QKV projections (tensor core, bf16-split)
    const int n4 = BT * DIM / 4;
    split_act<<<(n4 + 255) / 256, 256>>>(x, pah, pal, n4);
    gemm_nt_split<<<dim3(DIM / 128, BT / 128), 256>>>(pah, pal, pwqh, pwql, pq, BT, DIM, DIM);
    gemm_nt_split<<<dim3(NKV * HD / 128, BT / 128), 256>>>(pah, pal, pwkh, pwkl, pk, BT, NKV * HD, DIM);
    gemm_nt_split<<<dim3(NKV * HD / 128, BT / 128), 256>>>(pah, pal, pwvh, pwvl, pv, BT, NKV * HD, DIM);

    // 3) RMS norm + RoPE (+gain on q)
    rms_rope<<<dim3(BT, NH), 128>>>(pq, gain, NH, 1);
    rms_rope<<<dim3(BT, NKV), 128>>>(pk, gain, NKV, 0);

    // 4) causal flash attention
    size_t smem = (size_t)(3 * 64 * 129 + 64 * 65) * sizeof(float);
    cudaFuncSetAttribute(attn, cudaFuncAttributeMaxDynamicSharedMemorySize, (int)smem);
    attn<<<dim3(T / 64, Bb * NH), 256, smem>>>(pq, pk, pv, py, T);

    // 5) v-orthogonalization (in place on y)
    vorth<<<BT * NKV, 128>>>(pv, py);

    // 6) split y, output projection -> d_out (tensor core)
    split_act<<<(n4 + 255) / 256, 256>>>(py, pah, pal, n4);
    gemm_nt_split<<<dim3(DIM / 128, BT / 128), 256>>>(pah, pal, pwph, pwpl, (float*)d_out, BT, DIM, DIM);
}

// round 4
// speedup vs baseline: 2.3229x; 1.4703x over previous
#include <cuda_runtime.h>
#include <cuda_bf16.h>
#include <cstdint>
#include <math.h>

#define DIM  2048
#define NH   16
#define NKV  4
#define HD   128
#define GRP  (NH / NKV)
#define TSEQ 2048
#define BMAX 2

// ---------------- scratch (device globals; no allocation allowed) ----------
__device__ __nv_bfloat16 g_wq_h[DIM * DIM];
__device__ __nv_bfloat16 g_wq_l[DIM * DIM];
__device__ __nv_bfloat16 g_wk_h[NKV * HD * DIM];
__device__ __nv_bfloat16 g_wk_l[NKV * HD * DIM];
__device__ __nv_bfloat16 g_wv_h[NKV * HD * DIM];
__device__ __nv_bfloat16 g_wv_l[NKV * HD * DIM];
__device__ __nv_bfloat16 g_wp_h[DIM * DIM];
__device__ __nv_bfloat16 g_wp_l[DIM * DIM];
__device__ __nv_bfloat16 g_a_h[BMAX * TSEQ * DIM];   // activation split (x, then y)
__device__ __nv_bfloat16 g_a_l[BMAX * TSEQ * DIM];
__device__ float g_q[BMAX * TSEQ * DIM];
__device__ float g_k[BMAX * TSEQ * NKV * HD];
__device__ float g_v[BMAX * TSEQ * NKV * HD];
__device__ float g_y[BMAX * TSEQ * DIM];
// attention bf16-split operands
__device__ __nv_bfloat16 g_qh[BMAX * NH * TSEQ * HD];   // [b][h][t][d]
__device__ __nv_bfloat16 g_ql[BMAX * NH * TSEQ * HD];
__device__ __nv_bfloat16 g_kh[BMAX * NKV * TSEQ * HD];  // [b][kv][t][d]
__device__ __nv_bfloat16 g_kl[BMAX * NKV * TSEQ * HD];
__device__ __nv_bfloat16 g_vth[BMAX * NKV * HD * TSEQ]; // [b][kv][d][t]
__device__ __nv_bfloat16 g_vtl[BMAX * NKV * HD * TSEQ];

__device__ __forceinline__ void split_bf16(float v, __nv_bfloat16& h, __nv_bfloat16& l) {
    h = __float2bfloat16_rn(v);
    l = __float2bfloat16_rn(v - __bfloat162float(h));
}

__device__ __forceinline__ void split2_u32(float x, float y, uint32_t& h, uint32_t& l) {
    __nv_bfloat162 hh = __floats2bfloat162_rn(x, y);
    float rx = x - __bfloat162float(hh.x);
    float ry = y - __bfloat162float(hh.y);
    __nv_bfloat162 ll = __floats2bfloat162_rn(rx, ry);
    h = *(uint32_t*)&hh;
    l = *(uint32_t*)&ll;
}

// ---------------- weight quantization + bf16 split --------------------------
__global__ void prep_w(const float* __restrict__ w,
                       __nv_bfloat16* __restrict__ oh, __nv_bfloat16* __restrict__ ol,
                       const float* __restrict__ sfp) {
    const int row = blockIdx.x;
    const float* wr = w + (size_t)row * DIM;

    float part = 0.0f;
    for (int c = threadIdx.x; c < DIM; c += blockDim.x) part += fabsf(wr[c]);

    __shared__ float sh[8];
    #pragma unroll
    for (int off = 16; off; off >>= 1)
        part += __shfl_xor_sync(0xffffffffu, part, off);
    if ((threadIdx.x & 31) == 0) sh[threadIdx.x >> 5] = part;
    __syncthreads();
    float tot = 0.0f;
    #pragma unroll
    for (int i = 0; i < 8; i++) tot += sh[i];

    const float scale = fmaxf(tot * (1.0f / (float)DIM), 1e-8f);
    const float thr = 0.7f * scale;
    const float sf = *sfp;
    for (int c = threadIdx.x; c < DIM; c += blockDim.x) {
        float wv = wr[c];
        float wqv = (fabsf(wv) > thr) ? copysignf(scale, wv) : 0.0f;
        float eff = wv + sf * (wqv - wv);
        __nv_bfloat16 h, l;
        split_bf16(eff, h, l);
        oh[(size_t)row * DIM + c] = h;
        ol[(size_t)row * DIM + c] = l;
    }
}

// ---------------- fp32 -> bf16 hi/lo split for activations ------------------
__global__ void split_act(const float* __restrict__ in,
                          __nv_bfloat16* __restrict__ hi, __nv_bfloat16* __restrict__ lo,
                          int n4) {
    int i = blockIdx.x * blockDim.x + threadIdx.x;
    if (i >= n4) return;
    float4 v = ((const float4*)in)[i];
    __nv_bfloat16 h[4], l[4];
    split_bf16(v.x, h[0], l[0]);
    split_bf16(v.y, h[1], l[1]);
    split_bf16(v.z, h[2], l[2]);
    split_bf16(v.w, h[3], l[3]);
    ((uint2*)hi)[i] = *(uint2*)h;
    ((uint2*)lo)[i] = *(uint2*)l;
}

// ---------------- bf16-split tensor-core NT GEMM ----------------------------
#define LDS_K 40   // 32 + 8 halfs padding

__device__ __forceinline__ uint32_t lds_u32(const __nv_bfloat16* p) {
    return *(const uint32_t*)p;
}

__device__ __forceinline__ void mma_bf16(float d[4], const uint32_t a[4],
                                         const uint32_t b[2]) {
    asm volatile(
        "mma.sync.aligned.m16n8k16.row.col.f32.bf16.bf16.f32 "
        "{%0,%1,%2,%3}, {%4,%5,%6,%7}, {%8,%9}, {%0,%1,%2,%3};\n"
        : "+f"(d[0]), "+f"(d[1]), "+f"(d[2]), "+f"(d[3])
        : "r"(a[0]), "r"(a[1]), "r"(a[2]), "r"(a[3]), "r"(b[0]), "r"(b[1]));
}

__global__ __launch_bounds__(256)
void gemm_nt_split(const __nv_bfloat16* __restrict__ Ah, const __nv_bfloat16* __restrict__ Al,
                   const __nv_bfloat16* __restrict__ Bh, const __nv_bfloat16* __restrict__ Bl,
                   float* __restrict__ C, int M, int N, int K) {
    __shared__ __nv_bfloat16 sAh[128 * LDS_K];
    __shared__ __nv_bfloat16 sAl[128 * LDS_K];
    __shared__ __nv_bfloat16 sBh[128 * LDS_K];
    __shared__ __nv_bfloat16 sBl[128 * LDS_K];

    const int tid = threadIdx.x;
    const int lane = tid & 31;
    const int g = lane >> 2;
    const int tig = lane & 3;
    const int wm = (tid >> 5) & 1;
    const int wn = tid >> 6;
    const int m0 = blockIdx.y * 128;
    const int n0 = blockIdx.x * 128;

    float acc[4][4][4];
    #pragma unroll
    for (int i = 0; i < 4; i++)
        #pragma unroll
        for (int j = 0; j < 4; j++)
            #pragma unroll
            for (int r = 0; r < 4; r++) acc[i][j][r] = 0.0f;

    const int a_base = (wm * 64 + g) * LDS_K + tig * 2;
    const int b_base = (wn * 32 + g) * LDS_K + tig * 2;

    for (int k0 = 0; k0 < K; k0 += 32) {
        #pragma unroll
        for (int s = 0; s < 2; s++) {
            int chunk = tid + s * 256;
            int row = chunk >> 2;
            int part = chunk & 3;
            size_t goffA = (size_t)(m0 + row) * K + k0 + part * 8;
            size_t goffB = (size_t)(n0 + row) * K + k0 + part * 8;
            int soff = row * LDS_K + part * 8;
            *(uint4*)&sAh[soff] = *(const uint4*)&Ah[goffA];
            *(uint4*)&sAl[soff] = *(const uint4*)&Al[goffA];
            *(uint4*)&sBh[soff] = *(const uint4*)&Bh[goffB];
            *(uint4*)&sBl[soff] = *(const uint4*)&Bl[goffB];
        }
        __syncthreads();

        #pragma unroll
        for (int ks = 0; ks < 2; ks++) {
            const int koff = ks * 16;
            uint32_t af[4][4], bf_[4][2];

            #pragma unroll
            for (int i = 0; i < 4; i++) {
                int base = a_base + i * 16 * LDS_K + koff;
                af[i][0] = lds_u32(&sAh[base]);
                af[i][1] = lds_u32(&sAh[base + 8 * LDS_K]);
                af[i][2] = lds_u32(&sAh[base + 8]);
                af[i][3] = lds_u32(&sAh[base + 8 * LDS_K + 8]);
            }
            #pragma unroll
            for (int j = 0; j < 4; j++) {
                int base = b_base + j * 8 * LDS_K + koff;
                bf_[j][0] = lds_u32(&sBh[base]);
                bf_[j][1] = lds_u32(&sBh[base + 8]);
            }
            #pragma unroll
            for (int i = 0; i < 4; i++)
                #pragma unroll
                for (int j = 0; j < 4; j++) mma_bf16(acc[i][j], af[i], bf_[j]);

            #pragma unroll
            for (int j = 0; j < 4; j++) {
                int base = b_base + j * 8 * LDS_K + koff;
                bf_[j][0] = lds_u32(&sBl[base]);
                bf_[j][1] = lds_u32(&sBl[base + 8]);
            }
            #pragma unroll
            for (int i = 0; i < 4; i++)
                #pragma unroll
                for (int j = 0; j < 4; j++) mma_bf16(acc[i][j], af[i], bf_[j]);

            #pragma unroll
            for (int i = 0; i < 4; i++) {
                int base = a_base + i * 16 * LDS_K + koff;
                af[i][0] = lds_u32(&sAl[base]);
                af[i][1] = lds_u32(&sAl[base + 8 * LDS_K]);
                af[i][2] = lds_u32(&sAl[base + 8]);
                af[i][3] = lds_u32(&sAl[base + 8 * LDS_K + 8]);
            }
            #pragma unroll
            for (int j = 0; j < 4; j++) {
                int base = b_base + j * 8 * LDS_K + koff;
                bf_[j][0] = lds_u32(&sBh[base]);
                bf_[j][1] = lds_u32(&sBh[base + 8]);
            }
            #pragma unroll
            for (int i = 0; i < 4; i++)
                #pragma unroll
                for (int j = 0; j < 4; j++) mma_bf16(acc[i][j], af[i], bf_[j]);
        }
        __syncthreads();
    }

    #pragma unroll
    for (int i = 0; i < 4; i++) {
        #pragma unroll
        for (int j = 0; j < 4; j++) {
            int row1 = m0 + wm * 64 + i * 16 + g;
            int col = n0 + wn * 32 + j * 8 + tig * 2;
            float2 lo = make_float2(acc[i][j][0], acc[i][j][1]);
            float2 hi = make_float2(acc[i][j][2], acc[i][j][3]);
            *(float2*)&C[(size_t)row1 * N + col] = lo;
            *(float2*)&C[(size_t)(row1 + 8) * N + col] = hi;
        }
    }
}

// ---------------- fused RMSNorm + RoPE -> bf16 split, head-major layout -----
__global__ void rms_rope_split(const float* __restrict__ in,
                               __nv_bfloat16* __restrict__ oh, __nv_bfloat16* __restrict__ ol,
                               const float* __restrict__ gain, int heads, int T) {
    const int bt = blockIdx.x;
    const int hh = blockIdx.y;
    const int d = threadIdx.x;  // 128 threads
    const float* ptr = in + ((size_t)bt * heads + hh) * HD;

    float v = ptr[d];
    float ss = v * v;
    __shared__ float sh[4];
    #pragma unroll
    for (int off = 16; off; off >>= 1)
        ss += __shfl_xor_sync(0xffffffffu, ss, off);
    if ((d & 31) == 0) sh[d >> 5] = ss;
    __syncthreads();
    float tot = sh[0] + sh[1] + sh[2] + sh[3];
    float rs = rsqrtf(tot * (1.0f / (float)HD) + 1.1920928955078125e-07f);

    __shared__ float sn[HD];
    sn[d] = v * rs;
    __syncthreads();

    if (d < HD / 2) {
        const int b = bt / T;
        const int t = bt % T;
        float invf = 1.0f / powf(10000.0f, (float)d * (2.0f / (float)HD));
        float ang = (float)t * invf;
        float c = cosf(ang), s = sinf(ang);
        float x1 = sn[d], x2 = sn[d + HD / 2];
        float gq = gain ? gain[hh] : 1.0f;
        float o1 = (x1 * c + x2 * s) * gq;
        float o2 = (x2 * c - x1 * s) * gq;
        size_t obase = ((size_t)(b * heads + hh) * T + t) * HD;
        __nv_bfloat16 h1, l1, h2, l2;
        split_bf16(o1, h1, l1);
        split_bf16(o2, h2, l2);
        oh[obase + d] = h1;          ol[obase + d] = l1;
        oh[obase + d + HD / 2] = h2; ol[obase + d + HD / 2] = l2;
    }
}

// ---------------- V: split + transpose to [b][kv][d][t] ---------------------
__global__ void split_v_t(const float* __restrict__ v,
                          __nv_bfloat16* __restrict__ vth, __nv_bfloat16* __restrict__ vtl,
                          int T) {
    __shared__ float tile[32][33];
    const int bkv = blockIdx.z;
    const int b = bkv / NKV, kv = bkv % NKV;
    const int t0 = blockIdx.x * 32, d0 = blockIdx.y * 32;
    const int tx = threadIdx.x, ty = threadIdx.y;  // 32 x 8

    #pragma unroll
    for (int k = 0; k < 4; k++) {
        int t = t0 + ty + k * 8;
        tile[ty + k * 8][tx] = v[((size_t)(b * T + t) * NKV + kv) * HD + d0 + tx];
    }
    __syncthreads();
    #pragma unroll
    for (int k = 0; k < 4; k++) {
        int d = d0 + ty + k * 8;
        float val = tile[tx][ty + k * 8];
        __nv_bfloat16 h, l;
        split_bf16(val, h, l);
        size_t o = ((size_t)(b * NKV + kv) * HD + d) * T + t0 + tx;
        vth[o] = h;
        vtl[o] = l;
    }
}

// ---------------- causal flash attention (bf16-split tensor core) -----------
// 128 q rows per block, 64-k tiles, 8 warps x 16 rows, mma m16n8k16, 3-pass split.
#define ATT_QS 136
#define ATT_VS 72

__global__ __launch_bounds__(256, 1)
void attn_mma(const __nv_bfloat16* __restrict__ qh, const __nv_bfloat16* __restrict__ ql,
              const __nv_bfloat16* __restrict__ kh, const __nv_bfloat16* __restrict__ kl,
              const __nv_bfloat16* __restrict__ vth, const __nv_bfloat16* __restrict__ vtl,
              float* __restrict__ y, int T) {
    extern __shared__ __nv_bfloat16 smem_b[];
    __nv_bfloat16* sQh = smem_b;
    __nv_bfloat16* sQl = sQh + 128 * ATT_QS;
    __nv_bfloat16* sKh = sQl + 128 * ATT_QS;
    __nv_bfloat16* sKl = sKh + 64 * ATT_QS;
    __nv_bfloat16* sVh = sKl + 64 * ATT_QS;
    __nv_bfloat16* sVl = sVh + 128 * ATT_VS;

    const int qb = (gridDim.x - 1) - blockIdx.x;   // heavy blocks first
    const int bh = blockIdx.y;
    const int b = bh / NH, h = bh % NH, kv = h / GRP;
    const int tid = threadIdx.x;
    const int w = tid >> 5, lane = tid & 31, g = lane >> 2, tig = lane & 3;

    // load Q tile (128 x 128 bf16 hi/lo)
    {
        const size_t qbase = ((size_t)(b * NH + h) * T + qb * 128) * HD;
        for (int idx = tid; idx < 128 * 16; idx += 256) {
            int r = idx >> 4, dp = (idx & 15) * 8;
            *(uint4*)&sQh[r * ATT_QS + dp] = *(const uint4*)&qh[qbase + (size_t)r * HD + dp];
            *(uint4*)&sQl[r * ATT_QS + dp] = *(const uint4*)&ql[qbase + (size_t)r * HD + dp];
        }
    }

    float m_i[2] = {-1e30f, -1e30f};
    float l_i[2] = {0.0f, 0.0f};
    float O[16][4];
    #pragma unroll
    for (int jt = 0; jt < 16; jt++)
        #pragma unroll
        for (int r = 0; r < 4; r++) O[jt][r] = 0.0f;

    const float sc = 0.08838834764831845f;  // 1/sqrt(128)
    const int arow = w * 16 + g;
    const int nkb = 2 * qb + 2;

    for (int kb = 0; kb < nkb; kb++) {
        __syncthreads();
        {
            const size_t kbase = ((size_t)(b * NKV + kv) * T + kb * 64) * HD;
            for (int idx = tid; idx < 64 * 16; idx += 256) {
                int r = idx >> 4, dp = (idx & 15) * 8;
                *(uint4*)&sKh[r * ATT_QS + dp] = *(const uint4*)&kh[kbase + (size_t)r * HD + dp];
                *(uint4*)&sKl[r * ATT_QS + dp] = *(const uint4*)&kl[kbase + (size_t)r * HD + dp];
            }
            const size_t vbase = (size_t)(b * NKV + kv) * HD * T + kb * 64;
            for (int idx = tid; idx < 128 * 8; idx += 256) {
                int d = idx >> 3, kp = (idx & 7) * 8;
                *(uint4*)&sVh[d * ATT_VS + kp] = *(const uint4*)&vth[vbase + (size_t)d * T + kp];
                *(uint4*)&sVl[d * ATT_VS + kp] = *(const uint4*)&vtl[vbase + (size_t)d * T + kp];
            }
        }
        __syncthreads();

        // S = Q K^T  (3-pass split)
        float s[8][4];
        #pragma unroll
        for (int j = 0; j < 8; j++)
            #pragma unroll
            for (int r = 0; r < 4; r++) s[j][r] = 0.0f;

        #pragma unroll
        for (int kc = 0; kc < 8; kc++) {
            uint32_t ah[4], al[4];
            const int ab = arow * ATT_QS + kc * 16 + tig * 2;
            ah[0] = lds_u32(&sQh[ab]);
            ah[1] = lds_u32(&sQh[ab + 8 * ATT_QS]);
            ah[2] = lds_u32(&sQh[ab + 8]);
            ah[3] = lds_u32(&sQh[ab + 8 * ATT_QS + 8]);
            al[0] = lds_u32(&sQl[ab]);
            al[1] = lds_u32(&sQl[ab + 8 * ATT_QS]);
            al[2] = lds_u32(&sQl[ab + 8]);
            al[3] = lds_u32(&sQl[ab + 8 * ATT_QS + 8]);
            #pragma unroll
            for (int j = 0; j < 8; j++) {
                const int bb = (j * 8 + g) * ATT_QS + kc * 16 + tig * 2;
                uint32_t bh2[2], bl2[2];
                bh2[0] = lds_u32(&sKh[bb]);
                bh2[1] = lds_u32(&sKh[bb + 8]);
                bl2[0] = lds_u32(&sKl[bb]);
                bl2[1] = lds_u32(&sKl[bb + 8]);
                mma_bf16(s[j], ah, bh2);
                mma_bf16(s[j], al, bh2);
                mma_bf16(s[j], ah, bl2);
            }
        }

        // scale + causal mask
        const int row0 = qb * 128 + arow;
        const bool nomask = (kb * 64 + 63) <= (qb * 128 + w * 16);
        if (nomask) {
            #pragma unroll
            for (int j = 0; j < 8; j++)
                #pragma unroll
                for (int r = 0; r < 4; r++) s[j][r] *= sc;
        } else {
            #pragma unroll
            for (int j = 0; j < 8; j++) {
                const int c = kb * 64 + j * 8 + tig * 2;
                s[j][0] = (c     <= row0)     ? s[j][0] * sc : -1e30f;
                s[j][1] = (c + 1 <= row0)     ? s[j][1] * sc : -1e30f;
                s[j][2] = (c     <= row0 + 8) ? s[j][2] * sc : -1e30f;
                s[j][3] = (c + 1 <= row0 + 8) ? s[j][3] * sc : -1e30f;
            }
        }

        // online softmax (rows g and g+8)
        #pragma unroll
        for (int i = 0; i < 2; i++) {
            float rm = -1e30f;
            #pragma unroll
            for (int j = 0; j < 8; j++)
                rm = fmaxf(rm, fmaxf(s[j][2 * i], s[j][2 * i + 1]));
            rm = fmaxf(rm, __shfl_xor_sync(0xffffffffu, rm, 1));
            rm = fmaxf(rm, __shfl_xor_sync(0xffffffffu, rm, 2));
            const float mnew = fmaxf(m_i[i], rm);
            const float alpha = __expf(m_i[i] - mnew);
            float rs = 0.0f;
            #pragma unroll
            for (int j = 0; j < 8; j++) {
                s[j][2 * i]     = __expf(s[j][2 * i] - mnew);
                s[j][2 * i + 1] = __expf(s[j][2 * i + 1] - mnew);
                rs += s[j][2 * i] + s[j][2 * i + 1];
            }
            rs += __shfl_xor_sync(0xffffffffu, rs, 1);
            rs += __shfl_xor_sync(0xffffffffu, rs, 2);
            l_i[i] = l_i[i] * alpha + rs;
            m_i[i] = mnew;
            #pragma unroll
            for (int jt = 0; jt < 16; jt++) {
                O[jt][2 * i] *= alpha;
                O[jt][2 * i + 1] *= alpha;
            }
        }

        // O += P V  (3-pass split; P fragments built from S regs)
        #pragma unroll
        for (int kc = 0; kc < 4; kc++) {
            uint32_t ph[4], pl[4];
            split2_u32(s[2 * kc][0],     s[2 * kc][1],     ph[0], pl[0]);
            split2_u32(s[2 * kc][2],     s[2 * kc][3],     ph[1], pl[1]);
            split2_u32(s[2 * kc + 1][0], s[2 * kc + 1][1], ph[2], pl[2]);
            split2_u32(s[2 * kc + 1][2], s[2 * kc + 1][3], ph[3], pl[3]);
            #pragma unroll
            for (int jt = 0; jt < 16; jt++) {
                const int bb = (jt * 8 + g) * ATT_VS + kc * 16 + tig * 2;
                uint32_t bh2[2], bl2[2];
                bh2[0] = lds_u32(&sVh[bb]);
                bh2[1] = lds_u32(&sVh[bb + 8]);
                bl2[0] = lds_u32(&sVl[bb]);
                bl2[1] = lds_u32(&sVl[bb + 8]);
                mma_bf16(O[jt], ph, bh2);
                mma_bf16(O[jt], pl, bh2);
                mma_bf16(O[jt], ph, bl2);
            }
        }
    }

    // epilogue -> y [bt][h][d] fp32
    const float inv0 = 1.0f / l_i[0];
    const float inv1 = 1.0f / l_i[1];
    const int r0 = qb * 128 + arow;
    #pragma unroll
    for (int jt = 0; jt < 16; jt++) {
        const int col = jt * 8 + tig * 2;
        float2 v0 = make_float2(O[jt][0] * inv0, O[jt][1] * inv0);
        float2 v1 = make_float2(O[jt][2] * inv1, O[jt][3] * inv1);
        *(float2*)&y[((size_t)(b * T + r0) * NH + h) * HD + col] = v0;
        *(float2*)&y[((size_t)(b * T + r0 + 8) * NH + h) * HD + col] = v1;
    }
}

// ---------------- v-orthogonalization: y -= (y.vn) vn -----------------------
__device__ __forceinline__ float blk_sum_128(float val, float* sh) {
    #pragma unroll
    for (int off = 16; off; off >>= 1)
        val += __shfl_xor_sync(0xffffffffu, val, off);
    if ((threadIdx.x & 31) == 0) sh[threadIdx.x >> 5] = val;
    __syncthreads();
    float tot = sh[0] + sh[1] + sh[2] + sh[3];
    __syncthreads();
    return tot;
}

__global__ void vorth(const float* __restrict__ v, float* __restrict__ y) {
    __shared__ float sh[4];
    const int bt = blockIdx.x / NKV;
    const int kvh = blockIdx.x % NKV;
    const int d = threadIdx.x;  // 128

    float vv = v[((size_t)bt * NKV + kvh) * HD + d];
    float ss = blk_sum_128(vv * vv, sh);
    float nrm = sqrtf(ss);
    float vn = vv / fmaxf(nrm, 1e-12f);

    for (int g = 0; g < GRP; g++) {
        float* yp = y + ((size_t)bt * NH + kvh * GRP + g) * HD;
        float yv = yp[d];
        float dot = blk_sum_128(yv * vn, sh);
        yp[d] = yv - dot * vn;
    }
}

// ---------------- launcher ---------------------------------------------------
extern "C" void kernel_launch(void* const* d_in, const int* in_sizes, int n_in,
                              void* d_out, int out_size) {
    const float* x    = (const float*)d_in[0];
    const float* sfp  = (const float*)d_in[1];
    const float* wq   = (const float*)d_in[2];
    const float* wk   = (const float*)d_in[3];
    const float* wv   = (const float*)d_in[4];
    const float* wp   = (const float*)d_in[5];
    const float* gain = (const float*)d_in[6];

    const int BT = in_sizes[0] / DIM;   // B*T = 4096
    const int T = TSEQ;
    const int Bb = BT / T;

    __nv_bfloat16 *pwqh, *pwql, *pwkh, *pwkl, *pwvh, *pwvl, *pwph, *pwpl, *pah, *pal;
    __nv_bfloat16 *pqh, *pql, *pkh, *pkl, *pvth, *pvtl;
    float *pq, *pk, *pv, *py;
    cudaGetSymbolAddress((void**)&pwqh, g_wq_h);
    cudaGetSymbolAddress((void**)&pwql, g_wq_l);
    cudaGetSymbolAddress((void**)&pwkh, g_wk_h);
    cudaGetSymbolAddress((void**)&pwkl, g_wk_l);
    cudaGetSymbolAddress((void**)&pwvh, g_wv_h);
    cudaGetSymbolAddress((void**)&pwvl, g_wv_l);
    cudaGetSymbolAddress((void**)&pwph, g_wp_h);
    cudaGetSymbolAddress((void**)&pwpl, g_wp_l);
    cudaGetSymbolAddress((void**)&pah, g_a_h);
    cudaGetSymbolAddress((void**)&pal, g_a_l);
    cudaGetSymbolAddress((void**)&pqh, g_qh);
    cudaGetSymbolAddress((void**)&pql, g_ql);
    cudaGetSymbolAddress((void**)&pkh, g_kh);
    cudaGetSymbolAddress((void**)&pkl, g_kl);
    cudaGetSymbolAddress((void**)&pvth, g_vth);
    cudaGetSymbolAddress((void**)&pvtl, g_vtl);
    cudaGetSymbolAddress((void**)&pq, g_q);
    cudaGetSymbolAddress((void**)&pk, g_k);
    cudaGetSymbolAddress((void**)&pv, g_v);
    cudaGetSymbolAddress((void**)&py, g_y);

    // 1) effective weights -> bf16 hi/lo
    prep_w<<<DIM, 256>>>(wq, pwqh, pwql, sfp);
    prep_w<<<NKV * HD, 256>>>(wk, pwkh, pwkl, sfp);
    prep_w<<<NKV * HD, 256>>>(wv, pwvh, pwvl, sfp);
    prep_w<<<DIM, 256>>>(wp, pwph, pwpl, sfp);

    // 2) split x, QKV projections (tensor core, bf16-split)
    const int n4 = BT * DIM / 4;
    split_act<<<(n4 + 255) / 256, 256>>>(x, pah, pal, n4);
    gemm_nt_split<<<dim3(DIM / 128, BT / 128), 256>>>(pah, pal, pwqh, pwql, pq, BT, DIM, DIM);
    gemm_nt_split<<<dim3(NKV * HD / 128, BT / 128), 256>>>(pah, pal, pwkh, pwkl, pk, BT, NKV * HD, DIM);
    gemm_nt_split<<<dim3(NKV * HD / 128, BT / 128), 256>>>(pah, pal, pwvh, pwvl, pv, BT, NKV * HD, DIM);

    // 3) RMS norm + RoPE -> bf16 split, head-major; V split+transpose
    rms_rope_split<<<dim3(BT, NH), 128>>>(pq, pqh, pql, gain, NH, T);
    rms_rope_split<<<dim3(BT, NKV), 128>>>(pk, pkh, pkl, nullptr, NKV, T);
    split_v_t<<<dim3(T / 32, HD / 32, Bb * NKV), dim3(32, 8)>>>(pv, pvth, pvtl, T);

    // 4) causal flash attention (tensor core)
    size_t smem = (size_t)(2 * 128 * ATT_QS + 2 * 64 * ATT_QS + 2 * 128 * ATT_VS)
                  * sizeof(__nv_bfloat16);
    cudaFuncSetAttribute(attn_mma, cudaFuncAttributeMaxDynamicSharedMemorySize, (int)smem);
    attn_mma<<<dim3(T / 128, Bb * NH), 256, smem>>>(pqh, pql, pkh, pkl, pvth, pvtl, py, T);

    // 5) v-orthogonalization (in place on y)
    vorth<<<BT * NKV, 128>>>(pv, py);

    // 6) split y, output projection -> d_out (tensor core)
    split_act<<<(n4 + 255) / 256, 256>>>(py, pah, pal, n4);
    gemm_nt_split<<<dim3(DIM / 128, BT / 128), 256>>>(pah, pal, pwph, pwpl, (float*)d_out, BT, DIM, DIM);
}

// round 5
// speedup vs baseline: 3.0148x; 1.2979x over previous
#include <cuda_runtime.h>
#include <cuda_bf16.h>
#include <cstdint>
#include <math.h>

#define DIM  2048
#define NH   16
#define NKV  4
#define HD   128
#define GRP  (NH / NKV)
#define TSEQ 2048
#define BMAX 2

// ---------------- scratch (device globals; no allocation allowed) ----------
__device__ __nv_bfloat16 g_wq_h[DIM * DIM];
__device__ __nv_bfloat16 g_wq_l[DIM * DIM];
__device__ __nv_bfloat16 g_wk_h[NKV * HD * DIM];
__device__ __nv_bfloat16 g_wk_l[NKV * HD * DIM];
__device__ __nv_bfloat16 g_wv_h[NKV * HD * DIM];
__device__ __nv_bfloat16 g_wv_l[NKV * HD * DIM];
__device__ __nv_bfloat16 g_wp_h[DIM * DIM];
__device__ __nv_bfloat16 g_wp_l[DIM * DIM];
__device__ __nv_bfloat16 g_a_h[BMAX * TSEQ * DIM];
__device__ __nv_bfloat16 g_a_l[BMAX * TSEQ * DIM];
__device__ float g_q[BMAX * TSEQ * DIM];
__device__ float g_k[BMAX * TSEQ * NKV * HD];
__device__ float g_v[BMAX * TSEQ * NKV * HD];
__device__ float g_y[BMAX * TSEQ * DIM];
__device__ __nv_bfloat16 g_qh[BMAX * NH * TSEQ * HD];
__device__ __nv_bfloat16 g_ql[BMAX * NH * TSEQ * HD];
__device__ __nv_bfloat16 g_kh[BMAX * NKV * TSEQ * HD];
__device__ __nv_bfloat16 g_kl[BMAX * NKV * TSEQ * HD];
__device__ __nv_bfloat16 g_vth[BMAX * NKV * HD * TSEQ];
__device__ __nv_bfloat16 g_vtl[BMAX * NKV * HD * TSEQ];

__device__ __forceinline__ void split_bf16(float v, __nv_bfloat16& h, __nv_bfloat16& l) {
    h = __float2bfloat16_rn(v);
    l = __float2bfloat16_rn(v - __bfloat162float(h));
}

__device__ __forceinline__ void split2_u32(float x, float y, uint32_t& h, uint32_t& l) {
    __nv_bfloat162 hh = __floats2bfloat162_rn(x, y);
    float rx = x - __bfloat162float(hh.x);
    float ry = y - __bfloat162float(hh.y);
    __nv_bfloat162 ll = __floats2bfloat162_rn(rx, ry);
    h = *(uint32_t*)&hh;
    l = *(uint32_t*)&ll;
}

// ---------------- async copy + ldmatrix helpers ------------------------------
__device__ __forceinline__ void cp16(void* s, const void* g) {
    uint32_t sa = (uint32_t)__cvta_generic_to_shared(s);
    asm volatile("cp.async.cg.shared.global [%0], [%1], 16;\n" :: "r"(sa), "l"(g));
}
__device__ __forceinline__ void cp_commit() {
    asm volatile("cp.async.commit_group;\n");
}
template <int N>
__device__ __forceinline__ void cp_wait() {
    asm volatile("cp.async.wait_group %0;\n" :: "n"(N));
}
__device__ __forceinline__ void ldsm_x4(uint32_t& r0, uint32_t& r1, uint32_t& r2,
                                        uint32_t& r3, const __nv_bfloat16* p) {
    uint32_t a = (uint32_t)__cvta_generic_to_shared(p);
    asm volatile("ldmatrix.sync.aligned.m8n8.x4.shared.b16 {%0,%1,%2,%3}, [%4];\n"
                 : "=r"(r0), "=r"(r1), "=r"(r2), "=r"(r3) : "r"(a));
}

__device__ __forceinline__ void mma_bf16(float d[4], const uint32_t a[4],
                                         const uint32_t b[2]) {
    asm volatile(
        "mma.sync.aligned.m16n8k16.row.col.f32.bf16.bf16.f32 "
        "{%0,%1,%2,%3}, {%4,%5,%6,%7}, {%8,%9}, {%0,%1,%2,%3};\n"
        : "+f"(d[0]), "+f"(d[1]), "+f"(d[2]), "+f"(d[3])
        : "r"(a[0]), "r"(a[1]), "r"(a[2]), "r"(a[3]), "r"(b[0]), "r"(b[1]));
}

// ---------------- weight quantization + bf16 split --------------------------
__global__ void prep_w(const float* __restrict__ w,
                       __nv_bfloat16* __restrict__ oh, __nv_bfloat16* __restrict__ ol,
                       const float* __restrict__ sfp) {
    const int row = blockIdx.x;
    const float* wr = w + (size_t)row * DIM;

    float part = 0.0f;
    for (int c = threadIdx.x; c < DIM; c += blockDim.x) part += fabsf(wr[c]);

    __shared__ float sh[8];
    #pragma unroll
    for (int off = 16; off; off >>= 1)
        part += __shfl_xor_sync(0xffffffffu, part, off);
    if ((threadIdx.x & 31) == 0) sh[threadIdx.x >> 5] = part;
    __syncthreads();
    float tot = 0.0f;
    #pragma unroll
    for (int i = 0; i < 8; i++) tot += sh[i];

    const float scale = fmaxf(tot * (1.0f / (float)DIM), 1e-8f);
    const float thr = 0.7f * scale;
    const float sf = *sfp;
    for (int c = threadIdx.x; c < DIM; c += blockDim.x) {
        float wv = wr[c];
        float wqv = (fabsf(wv) > thr) ? copysignf(scale, wv) : 0.0f;
        float eff = wv + sf * (wqv - wv);
        __nv_bfloat16 h, l;
        split_bf16(eff, h, l);
        oh[(size_t)row * DIM + c] = h;
        ol[(size_t)row * DIM + c] = l;
    }
}

// ---------------- fp32 -> bf16 hi/lo split for activations ------------------
__global__ void split_act(const float* __restrict__ in,
                          __nv_bfloat16* __restrict__ hi, __nv_bfloat16* __restrict__ lo,
                          int n4) {
    int i = blockIdx.x * blockDim.x + threadIdx.x;
    if (i >= n4) return;
    float4 v = ((const float4*)in)[i];
    __nv_bfloat16 h[4], l[4];
    split_bf16(v.x, h[0], l[0]);
    split_bf16(v.y, h[1], l[1]);
    split_bf16(v.z, h[2], l[2]);
    split_bf16(v.w, h[3], l[3]);
    ((uint2*)hi)[i] = *(uint2*)h;
    ((uint2*)lo)[i] = *(uint2*)l;
}

// ---------------- bf16-split tensor-core NT GEMM (ldmatrix + cp.async) ------
#define LDS_K 40
#define GSTG (128 * LDS_K)   // halfs per array per stage

__global__ __launch_bounds__(256, 1)
void gemm_nt_split(const __nv_bfloat16* __restrict__ Ah, const __nv_bfloat16* __restrict__ Al,
                   const __nv_bfloat16* __restrict__ Bh, const __nv_bfloat16* __restrict__ Bl,
                   float* __restrict__ C, int M, int N, int K) {
    extern __shared__ __nv_bfloat16 sm[];
    // stage st: sm + st*4*GSTG; arrays: Ah, Al, Bh, Bl

    const int tid = threadIdx.x;
    const int lane = tid & 31;
    const int wm = (tid >> 5) & 1;
    const int wn = tid >> 6;
    const int m0 = blockIdx.y * 128;
    const int n0 = blockIdx.x * 128;

    float acc[4][4][4];
    #pragma unroll
    for (int i = 0; i < 4; i++)
        #pragma unroll
        for (int j = 0; j < 4; j++)
            #pragma unroll
            for (int r = 0; r < 4; r++) acc[i][j][r] = 0.0f;

    // ldmatrix per-thread source offsets (halfs)
    const int aoff = (wm * 64 + (lane & 15)) * LDS_K + (lane >> 4) * 8;
    const int boff = (wn * 32 + ((lane >> 4) & 1) * 8 + (lane & 7)) * LDS_K
                     + ((lane >> 3) & 1) * 8;

    const int ntiles = K / 32;

    // stage loader: 4 arrays x 512 uint4, 8 cp.async per thread
    auto load_stage = [&](int st, int k0) {
        __nv_bfloat16* base = sm + st * 4 * GSTG;
        #pragma unroll
        for (int s2 = 0; s2 < 2; s2++) {
            int chunk = tid + s2 * 256;
            int row = chunk >> 2;
            int part = chunk & 3;
            size_t goA = (size_t)(m0 + row) * K + k0 + part * 8;
            size_t goB = (size_t)(n0 + row) * K + k0 + part * 8;
            int so = row * LDS_K + part * 8;
            cp16(base + so, Ah + goA);
            cp16(base + GSTG + so, Al + goA);
            cp16(base + 2 * GSTG + so, Bh + goB);
            cp16(base + 3 * GSTG + so, Bl + goB);
        }
    };

    load_stage(0, 0);
    cp_commit();

    for (int kt = 0; kt < ntiles; kt++) {
        if (kt + 1 < ntiles) {
            load_stage((kt + 1) & 1, (kt + 1) * 32);
            cp_commit();
            cp_wait<1>();
        } else {
            cp_wait<0>();
        }
        __syncthreads();

        const __nv_bfloat16* sAh = sm + (kt & 1) * 4 * GSTG;
        const __nv_bfloat16* sAl = sAh + GSTG;
        const __nv_bfloat16* sBh = sAh + 2 * GSTG;
        const __nv_bfloat16* sBl = sAh + 3 * GSTG;

        #pragma unroll
        for (int ks = 0; ks < 2; ks++) {
            const int ko = ks * 16;
            uint32_t ah[4][4], al[4][4], bh[4][2], bl[4][2];
            #pragma unroll
            for (int i = 0; i < 4; i++) {
                ldsm_x4(ah[i][0], ah[i][1], ah[i][2], ah[i][3],
                        sAh + aoff + i * 16 * LDS_K + ko);
                ldsm_x4(al[i][0], al[i][1], al[i][2], al[i][3],
                        sAl + aoff + i * 16 * LDS_K + ko);
            }
            #pragma unroll
            for (int jp = 0; jp < 2; jp++) {
                ldsm_x4(bh[2 * jp][0], bh[2 * jp][1], bh[2 * jp + 1][0], bh[2 * jp + 1][1],
                        sBh + boff + jp * 16 * LDS_K + ko);
                ldsm_x4(bl[2 * jp][0], bl[2 * jp][1], bl[2 * jp + 1][0], bl[2 * jp + 1][1],
                        sBl + boff + jp * 16 * LDS_K + ko);
            }
            #pragma unroll
            for (int i = 0; i < 4; i++)
                #pragma unroll
                for (int j = 0; j < 4; j++) mma_bf16(acc[i][j], ah[i], bh[j]);
            #pragma unroll
            for (int i = 0; i < 4; i++)
                #pragma unroll
                for (int j = 0; j < 4; j++) mma_bf16(acc[i][j], ah[i], bl[j]);
            #pragma unroll
            for (int i = 0; i < 4; i++)
                #pragma unroll
                for (int j = 0; j < 4; j++) mma_bf16(acc[i][j], al[i], bh[j]);
        }
        __syncthreads();
    }

    const int g = lane >> 2, tig = lane & 3;
    #pragma unroll
    for (int i = 0; i < 4; i++) {
        #pragma unroll
        for (int j = 0; j < 4; j++) {
            int row1 = m0 + wm * 64 + i * 16 + g;
            int col = n0 + wn * 32 + j * 8 + tig * 2;
            float2 lo = make_float2(acc[i][j][0], acc[i][j][1]);
            float2 hi = make_float2(acc[i][j][2], acc[i][j][3]);
            *(float2*)&C[(size_t)row1 * N + col] = lo;
            *(float2*)&C[(size_t)(row1 + 8) * N + col] = hi;
        }
    }
}

// ---------------- fused RMSNorm + RoPE -> bf16 split, head-major layout -----
__global__ void rms_rope_split(const float* __restrict__ in,
                               __nv_bfloat16* __restrict__ oh, __nv_bfloat16* __restrict__ ol,
                               const float* __restrict__ gain, int heads, int T) {
    const int bt = blockIdx.x;
    const int hh = blockIdx.y;
    const int d = threadIdx.x;
    const float* ptr = in + ((size_t)bt * heads + hh) * HD;

    float v = ptr[d];
    float ss = v * v;
    __shared__ float sh[4];
    #pragma unroll
    for (int off = 16; off; off >>= 1)
        ss += __shfl_xor_sync(0xffffffffu, ss, off);
    if ((d & 31) == 0) sh[d >> 5] = ss;
    __syncthreads();
    float tot = sh[0] + sh[1] + sh[2] + sh[3];
    float rs = rsqrtf(tot * (1.0f / (float)HD) + 1.1920928955078125e-07f);

    __shared__ float sn[HD];
    sn[d] = v * rs;
    __syncthreads();

    if (d < HD / 2) {
        const int b = bt / T;
        const int t = bt % T;
        float invf = 1.0f / powf(10000.0f, (float)d * (2.0f / (float)HD));
        float ang = (float)t * invf;
        float c = cosf(ang), s = sinf(ang);
        float x1 = sn[d], x2 = sn[d + HD / 2];
        float gq = gain ? gain[hh] : 1.0f;
        float o1 = (x1 * c + x2 * s) * gq;
        float o2 = (x2 * c - x1 * s) * gq;
        size_t obase = ((size_t)(b * heads + hh) * T + t) * HD;
        __nv_bfloat16 h1, l1, h2, l2;
        split_bf16(o1, h1, l1);
        split_bf16(o2, h2, l2);
        oh[obase + d] = h1;          ol[obase + d] = l1;
        oh[obase + d + HD / 2] = h2; ol[obase + d + HD / 2] = l2;
    }
}

// ---------------- V: split + transpose to [b][kv][d][t] ---------------------
__global__ void split_v_t(const float* __restrict__ v,
                          __nv_bfloat16* __restrict__ vth, __nv_bfloat16* __restrict__ vtl,
                          int T) {
    __shared__ float tile[32][33];
    const int bkv = blockIdx.z;
    const int b = bkv / NKV, kv = bkv % NKV;
    const int t0 = blockIdx.x * 32, d0 = blockIdx.y * 32;
    const int tx = threadIdx.x, ty = threadIdx.y;

    #pragma unroll
    for (int k = 0; k < 4; k++) {
        int t = t0 + ty + k * 8;
        tile[ty + k * 8][tx] = v[((size_t)(b * T + t) * NKV + kv) * HD + d0 + tx];
    }
    __syncthreads();
    #pragma unroll
    for (int k = 0; k < 4; k++) {
        int d = d0 + ty + k * 8;
        float val = tile[tx][ty + k * 8];
        __nv_bfloat16 h, l;
        split_bf16(val, h, l);
        size_t o = ((size_t)(b * NKV + kv) * HD + d) * T + t0 + tx;
        vth[o] = h;
        vtl[o] = l;
    }
}

// ---------------- causal flash attention (bf16-split TC, ldmatrix+cp.async) -
#define ATT_QS 136
#define ATT_VS 72
#define KV_STG (64 * ATT_QS * 2 + 128 * ATT_VS * 2)  // halfs per K/V stage (Kh,Kl,Vh,Vl)

__global__ __launch_bounds__(256, 1)
void attn_mma(const __nv_bfloat16* __restrict__ qh, const __nv_bfloat16* __restrict__ ql,
              const __nv_bfloat16* __restrict__ kh, const __nv_bfloat16* __restrict__ kl,
              const __nv_bfloat16* __restrict__ vth, const __nv_bfloat16* __restrict__ vtl,
              float* __restrict__ y, int T) {
    extern __shared__ __nv_bfloat16 smem_b[];
    __nv_bfloat16* sQh = smem_b;                       // 128 x ATT_QS
    __nv_bfloat16* sQl = sQh + 128 * ATT_QS;
    __nv_bfloat16* sKV = sQl + 128 * ATT_QS;           // 2 stages
    // within stage: Kh (64*ATT_QS), Kl, Vh (128*ATT_VS), Vl

    const int qb = (gridDim.x - 1) - blockIdx.x;
    const int bh = blockIdx.y;
    const int b = bh / NH, h = bh % NH, kv = h / GRP;
    const int tid = threadIdx.x;
    const int w = tid >> 5, lane = tid & 31, g = lane >> 2, tig = lane & 3;

    const size_t kbase0 = (size_t)(b * NKV + kv) * T * HD;
    const size_t vbase0 = (size_t)(b * NKV + kv) * HD * T;

    // K/V stage loader: 8 cp.async per thread
    auto load_kv = [&](int st, int kb) {
        __nv_bfloat16* base = sKV + st * KV_STG;
        __nv_bfloat16* bKh = base;
        __nv_bfloat16* bKl = base + 64 * ATT_QS;
        __nv_bfloat16* bVh = base + 2 * 64 * ATT_QS;
        __nv_bfloat16* bVl = bVh + 128 * ATT_VS;
        const size_t kbase = kbase0 + (size_t)kb * 64 * HD;
        #pragma unroll
        for (int s2 = 0; s2 < 4; s2++) {
            int idx = tid + s2 * 256;        // 0..1023
            int r = idx >> 4, dp = (idx & 15) * 8;
            cp16(bKh + r * ATT_QS + dp, kh + kbase + (size_t)r * HD + dp);
            cp16(bKl + r * ATT_QS + dp, kl + kbase + (size_t)r * HD + dp);
        }
        const size_t vbase = vbase0 + (size_t)kb * 64;
        #pragma unroll
        for (int s2 = 0; s2 < 4; s2++) {
            int idx = tid + s2 * 256;        // 0..1023
            int d = idx >> 3, kp = (idx & 7) * 8;
            cp16(bVh + d * ATT_VS + kp, vth + vbase + (size_t)d * T + kp);
            cp16(bVl + d * ATT_VS + kp, vtl + vbase + (size_t)d * T + kp);
        }
    };

    const int nkb = 2 * qb + 2;
    load_kv(0, 0);
    cp_commit();

    // Q tile (regular loads)
    {
        const size_t qbase = ((size_t)(b * NH + h) * T + qb * 128) * HD;
        for (int idx = tid; idx < 128 * 16; idx += 256) {
            int r = idx >> 4, dp = (idx & 15) * 8;
            *(uint4*)&sQh[r * ATT_QS + dp] = *(const uint4*)&qh[qbase + (size_t)r * HD + dp];
            *(uint4*)&sQl[r * ATT_QS + dp] = *(const uint4*)&ql[qbase + (size_t)r * HD + dp];
        }
    }

    float m_i[2] = {-1e30f, -1e30f};
    float l_i[2] = {0.0f, 0.0f};
    float O[16][4];
    #pragma unroll
    for (int jt = 0; jt < 16; jt++)
        #pragma unroll
        for (int r = 0; r < 4; r++) O[jt][r] = 0.0f;

    const float sc = 0.08838834764831845f;
    const int arow = w * 16;

    // ldmatrix per-thread offsets (halfs)
    const int qoff = (arow + (lane & 15)) * ATT_QS + (lane >> 4) * 8;
    const int koff_f = (((lane >> 4) & 1) * 8 + (lane & 7)) * ATT_QS + ((lane >> 3) & 1) * 8;
    const int voff_f = (((lane >> 4) & 1) * 8 + (lane & 7)) * ATT_VS + ((lane >> 3) & 1) * 8;

    for (int kb = 0; kb < nkb; kb++) {
        if (kb + 1 < nkb) {
            load_kv((kb + 1) & 1, kb + 1);
            cp_commit();
            cp_wait<1>();
        } else {
            cp_wait<0>();
        }
        __syncthreads();

        const __nv_bfloat16* bKh = sKV + (kb & 1) * KV_STG;
        const __nv_bfloat16* bKl = bKh + 64 * ATT_QS;
        const __nv_bfloat16* bVh = bKh + 2 * 64 * ATT_QS;
        const __nv_bfloat16* bVl = bVh + 128 * ATT_VS;

        // S = Q K^T (3-pass split)
        float s[8][4];
        #pragma unroll
        for (int j = 0; j < 8; j++)
            #pragma unroll
            for (int r = 0; r < 4; r++) s[j][r] = 0.0f;

        #pragma unroll
        for (int kc = 0; kc < 8; kc++) {
            const int ko = kc * 16;
            uint32_t ah[4], al[4];
            ldsm_x4(ah[0], ah[1], ah[2], ah[3], sQh + qoff + ko);
            ldsm_x4(al[0], al[1], al[2], al[3], sQl + qoff + ko);
            #pragma unroll
            for (int jp = 0; jp < 4; jp++) {
                uint32_t kh4[4], kl4[4];
                ldsm_x4(kh4[0], kh4[1], kh4[2], kh4[3],
                        bKh + koff_f + jp * 16 * ATT_QS + ko);
                ldsm_x4(kl4[0], kl4[1], kl4[2], kl4[3],
                        bKl + koff_f + jp * 16 * ATT_QS + ko);
                mma_bf16(s[2 * jp],     ah, &kh4[0]);
                mma_bf16(s[2 * jp],     al, &kh4[0]);
                mma_bf16(s[2 * jp],     ah, &kl4[0]);
                mma_bf16(s[2 * jp + 1], ah, &kh4[2]);
                mma_bf16(s[2 * jp + 1], al, &kh4[2]);
                mma_bf16(s[2 * jp + 1], ah, &kl4[2]);
            }
        }

        // scale + causal mask
        const int row0 = qb * 128 + arow + g;
        const bool nomask = (kb * 64 + 63) <= (qb * 128 + arow);
        if (nomask) {
            #pragma unroll
            for (int j = 0; j < 8; j++)
                #pragma unroll
                for (int r = 0; r < 4; r++) s[j][r] *= sc;
        } else {
            #pragma unroll
            for (int j = 0; j < 8; j++) {
                const int c = kb * 64 + j * 8 + tig * 2;
                s[j][0] = (c     <= row0)     ? s[j][0] * sc : -1e30f;
                s[j][1] = (c + 1 <= row0)     ? s[j][1] * sc : -1e30f;
                s[j][2] = (c     <= row0 + 8) ? s[j][2] * sc : -1e30f;
                s[j][3] = (c + 1 <= row0 + 8) ? s[j][3] * sc : -1e30f;
            }
        }

        // online softmax (rows g and g+8)
        #pragma unroll
        for (int i = 0; i < 2; i++) {
            float rm = -1e30f;
            #pragma unroll
            for (int j = 0; j < 8; j++)
                rm = fmaxf(rm, fmaxf(s[j][2 * i], s[j][2 * i + 1]));
            rm = fmaxf(rm, __shfl_xor_sync(0xffffffffu, rm, 1));
            rm = fmaxf(rm, __shfl_xor_sync(0xffffffffu, rm, 2));
            const float mnew = fmaxf(m_i[i], rm);
            const float alpha = __expf(m_i[i] - mnew);
            float rs = 0.0f;
            #pragma unroll
            for (int j = 0; j < 8; j++) {
                s[j][2 * i]     = __expf(s[j][2 * i] - mnew);
                s[j][2 * i + 1] = __expf(s[j][2 * i + 1] - mnew);
                rs += s[j][2 * i] + s[j][2 * i + 1];
            }
            rs += __shfl_xor_sync(0xffffffffu, rs, 1);
            rs += __shfl_xor_sync(0xffffffffu, rs, 2);
            l_i[i] = l_i[i] * alpha + rs;
            m_i[i] = mnew;
            #pragma unroll
            for (int jt = 0; jt < 16; jt++) {
                O[jt][2 * i] *= alpha;
                O[jt][2 * i + 1] *= alpha;
            }
        }

        // O += P V (3-pass split)
        #pragma unroll
        for (int kc = 0; kc < 4; kc++) {
            const int ko = kc * 16;
            uint32_t ph[4], pl[4];
            split2_u32(s[2 * kc][0],     s[2 * kc][1],     ph[0], pl[0]);
            split2_u32(s[2 * kc][2],     s[2 * kc][3],     ph[1], pl[1]);
            split2_u32(s[2 * kc + 1][0], s[2 * kc + 1][1], ph[2], pl[2]);
            split2_u32(s[2 * kc + 1][2], s[2 * kc + 1][3], ph[3], pl[3]);
            #pragma unroll
            for (int jp = 0; jp < 8; jp++) {
                uint32_t vh4[4], vl4[4];
                ldsm_x4(vh4[0], vh4[1], vh4[2], vh4[3],
                        bVh + voff_f + jp * 16 * ATT_VS + ko);
                ldsm_x4(vl4[0], vl4[1], vl4[2], vl4[3],
                        bVl + voff_f + jp * 16 * ATT_VS + ko);
                mma_bf16(O[2 * jp],     ph, &vh4[0]);
                mma_bf16(O[2 * jp],     pl, &vh4[0]);
                mma_bf16(O[2 * jp],     ph, &vl4[0]);
                mma_bf16(O[2 * jp + 1], ph, &vh4[2]);
                mma_bf16(O[2 * jp + 1], pl, &vh4[2]);
                mma_bf16(O[2 * jp + 1], ph, &vl4[2]);
            }
        }
        __syncthreads();
    }

    // epilogue -> y [bt][h][d] fp32
    const float inv0 = 1.0f / l_i[0];
    const float inv1 = 1.0f / l_i[1];
    const int r0 = qb * 128 + arow + g;
    #pragma unroll
    for (int jt = 0; jt < 16; jt++) {
        const int col = jt * 8 + tig * 2;
        float2 v0 = make_float2(O[jt][0] * inv0, O[jt][1] * inv0);
        float2 v1 = make_float2(O[jt][2] * inv1, O[jt][3] * inv1);
        *(float2*)&y[((size_t)(b * T + r0) * NH + h) * HD + col] = v0;
        *(float2*)&y[((size_t)(b * T + r0 + 8) * NH + h) * HD + col] = v1;
    }
}

// ---------------- v-orthogonalization: y -= (y.vn) vn -----------------------
__device__ __forceinline__ float blk_sum_128(float val, float* sh) {
    #pragma unroll
    for (int off = 16; off; off >>= 1)
        val += __shfl_xor_sync(0xffffffffu, val, off);
    if ((threadIdx.x & 31) == 0) sh[threadIdx.x >> 5] = val;
    __syncthreads();
    float tot = sh[0] + sh[1] + sh[2] + sh[3];
    __syncthreads();
    return tot;
}

__global__ void vorth(const float* __restrict__ v, float* __restrict__ y) {
    __shared__ float sh[4];
    const int bt = blockIdx.x / NKV;
    const int kvh = blockIdx.x % NKV;
    const int d = threadIdx.x;

    float vv = v[((size_t)bt * NKV + kvh) * HD + d];
    float ss = blk_sum_128(vv * vv, sh);
    float nrm = sqrtf(ss);
    float vn = vv / fmaxf(nrm, 1e-12f);

    for (int g = 0; g < GRP; g++) {
        float* yp = y + ((size_t)bt * NH + kvh * GRP + g) * HD;
        float yv = yp[d];
        float dot = blk_sum_128(yv * vn, sh);
        yp[d] = yv - dot * vn;
    }
}

// ---------------- launcher ---------------------------------------------------
extern "C" void kernel_launch(void* const* d_in, const int* in_sizes, int n_in,
                              void* d_out, int out_size) {
    const float* x    = (const float*)d_in[0];
    const float* sfp  = (const float*)d_in[1];
    const float* wq   = (const float*)d_in[2];
    const float* wk   = (const float*)d_in[3];
    const float* wv   = (const float*)d_in[4];
    const float* wp   = (const float*)d_in[5];
    const float* gain = (const float*)d_in[6];

    const int BT = in_sizes[0] / DIM;
    const int T = TSEQ;
    const int Bb = BT / T;

    __nv_bfloat16 *pwqh, *pwql, *pwkh, *pwkl, *pwvh, *pwvl, *pwph, *pwpl, *pah, *pal;
    __nv_bfloat16 *pqh, *pql, *pkh, *pkl, *pvth, *pvtl;
    float *pq, *pk, *pv, *py;
    cudaGetSymbolAddress((void**)&pwqh, g_wq_h);
    cudaGetSymbolAddress((void**)&pwql, g_wq_l);
    cudaGetSymbolAddress((void**)&pwkh, g_wk_h);
    cudaGetSymbolAddress((void**)&pwkl, g_wk_l);
    cudaGetSymbolAddress((void**)&pwvh, g_wv_h);
    cudaGetSymbolAddress((void**)&pwvl, g_wv_l);
    cudaGetSymbolAddress((void**)&pwph, g_wp_h);
    cudaGetSymbolAddress((void**)&pwpl, g_wp_l);
    cudaGetSymbolAddress((void**)&pah, g_a_h);
    cudaGetSymbolAddress((void**)&pal, g_a_l);
    cudaGetSymbolAddress((void**)&pqh, g_qh);
    cudaGetSymbolAddress((void**)&pql, g_ql);
    cudaGetSymbolAddress((void**)&pkh, g_kh);
    cudaGetSymbolAddress((void**)&pkl, g_kl);
    cudaGetSymbolAddress((void**)&pvth, g_vth);
    cudaGetSymbolAddress((void**)&pvtl, g_vtl);
    cudaGetSymbolAddress((void**)&pq, g_q);
    cudaGetSymbolAddress((void**)&pk, g_k);
    cudaGetSymbolAddress((void**)&pv, g_v);
    cudaGetSymbolAddress((void**)&py, g_y);

    // 1) effective weights -> bf16 hi/lo
    prep_w<<<DIM, 256>>>(wq, pwqh, pwql, sfp);
    prep_w<<<NKV * HD, 256>>>(wk, pwkh, pwkl, sfp);
    prep_w<<<NKV * HD, 256>>>(wv, pwvh, pwvl, sfp);
    prep_w<<<DIM, 256>>>(wp, pwph, pwpl, sfp);

    // 2) split x, QKV projections
    const int n4 = BT * DIM / 4;
    const size_t gsmem = (size_t)2 * 4 * GSTG * sizeof(__nv_bfloat16);  // 81920
    cudaFuncSetAttribute(gemm_nt_split, cudaFuncAttributeMaxDynamicSharedMemorySize, (int)gsmem);
    split_act<<<(n4 + 255) / 256, 256>>>(x, pah, pal, n4);
    gemm_nt_split<<<dim3(DIM / 128, BT / 128), 256, gsmem>>>(pah, pal, pwqh, pwql, pq, BT, DIM, DIM);
    gemm_nt_split<<<dim3(NKV * HD / 128, BT / 128), 256, gsmem>>>(pah, pal, pwkh, pwkl, pk, BT, NKV * HD, DIM);
    gemm_nt_split<<<dim3(NKV * HD / 128, BT / 128), 256, gsmem>>>(pah, pal, pwvh, pwvl, pv, BT, NKV * HD, DIM);

    // 3) RMS norm + RoPE -> bf16 split, head-major; V split+transpose
    rms_rope_split<<<dim3(BT, NH), 128>>>(pq, pqh, pql, gain, NH, T);
    rms_rope_split<<<dim3(BT, NKV), 128>>>(pk, pkh, pkl, nullptr, NKV, T);
    split_v_t<<<dim3(T / 32, HD / 32, Bb * NKV), dim3(32, 8)>>>(pv, pvth, pvtl, T);

    // 4) causal flash attention (tensor core, ldmatrix + cp.async dbuf)
    size_t asmem = (size_t)(2 * 128 * ATT_QS + 2 * KV_STG) * sizeof(__nv_bfloat16);
    cudaFuncSetAttribute(attn_mma, cudaFuncAttributeMaxDynamicSharedMemorySize, (int)asmem);
    attn_mma<<<dim3(T / 128, Bb * NH), 256, asmem>>>(pqh, pql, pkh, pkl, pvth, pvtl, py, T);

    // 5) v-orthogonalization (in place on y)
    vorth<<<BT * NKV, 128>>>(pv, py);

    // 6) split y, output projection -> d_out
    split_act<<<(n4 + 255) / 256, 256>>>(py, pah, pal, n4);
    gemm_nt_split<<<dim3(DIM / 128, BT / 128), 256, gsmem>>>(pah, pal, pwph, pwpl, (float*)d_out, BT, DIM, DIM);
}

// round 7
// speedup vs baseline: 3.3375x; 1.1070x over previous
#include <cuda_runtime.h>
#include <cuda_bf16.h>
#include <cstdint>
#include <math.h>

#define DIM  2048
#define NH   16
#define NKV  4
#define HD   128
#define GRP  (NH / NKV)
#define TSEQ 2048
#define BMAX 2
#define KVW  (2 * NKV * HD)   // 1024: merged K|V projection width

// ---------------- scratch (device globals; no allocation allowed) ----------
__device__ __nv_bfloat16 g_wq_h[DIM * DIM];
__device__ __nv_bfloat16 g_wq_l[DIM * DIM];
__device__ __nv_bfloat16 g_wkv_h[KVW * DIM];
__device__ __nv_bfloat16 g_wkv_l[KVW * DIM];
__device__ __nv_bfloat16 g_wp_h[DIM * DIM];
__device__ __nv_bfloat16 g_wp_l[DIM * DIM];
__device__ __nv_bfloat16 g_a_h[BMAX * TSEQ * DIM];   // activation split (x, then y)
__device__ __nv_bfloat16 g_a_l[BMAX * TSEQ * DIM];
__device__ float g_q[BMAX * TSEQ * DIM];
__device__ float g_kv[BMAX * TSEQ * KVW];            // [bt][K(512)|V(512)]
__device__ float g_vn[BMAX * TSEQ * NKV * HD];       // normalized V
__device__ __nv_bfloat16 g_qh[BMAX * NH * TSEQ * HD];
__device__ __nv_bfloat16 g_ql[BMAX * NH * TSEQ * HD];
__device__ __nv_bfloat16 g_kh[BMAX * NKV * TSEQ * HD];
__device__ __nv_bfloat16 g_kl[BMAX * NKV * TSEQ * HD];
__device__ __nv_bfloat16 g_vth[BMAX * NKV * HD * TSEQ];
__device__ __nv_bfloat16 g_vtl[BMAX * NKV * HD * TSEQ];

__device__ __forceinline__ void split_bf16(float v, __nv_bfloat16& h, __nv_bfloat16& l) {
    h = __float2bfloat16_rn(v);
    l = __float2bfloat16_rn(v - __bfloat162float(h));
}

__device__ __forceinline__ void split2_u32(float x, float y, uint32_t& h, uint32_t& l) {
    __nv_bfloat162 hh = __floats2bfloat162_rn(x, y);
    float rx = x - __bfloat162float(hh.x);
    float ry = y - __bfloat162float(hh.y);
    __nv_bfloat162 ll = __floats2bfloat162_rn(rx, ry);
    h = *(uint32_t*)&hh;
    l = *(uint32_t*)&ll;
}

// ---------------- async copy / ldmatrix / mma.sync helpers ------------------
__device__ __forceinline__ uint32_t smem_u32(const void* p) {
    return (uint32_t)__cvta_generic_to_shared(p);
}
__device__ __forceinline__ void cp16(void* s, const void* g) {
    asm volatile("cp.async.cg.shared.global [%0], [%1], 16;\n"
                 :: "r"(smem_u32(s)), "l"(g));
}
__device__ __forceinline__ void cp_commit() {
    asm volatile("cp.async.commit_group;\n");
}
template <int N>
__device__ __forceinline__ void cp_wait() {
    asm volatile("cp.async.wait_group %0;\n" :: "n"(N));
}
__device__ __forceinline__ void ldsm_x4(uint32_t& r0, uint32_t& r1, uint32_t& r2,
                                        uint32_t& r3, const __nv_bfloat16* p) {
    asm volatile("ldmatrix.sync.aligned.m8n8.x4.shared.b16 {%0,%1,%2,%3}, [%4];\n"
                 : "=r"(r0), "=r"(r1), "=r"(r2), "=r"(r3) : "r"(smem_u32(p)));
}
__device__ __forceinline__ void mma_bf16(float d[4], const uint32_t a[4],
                                         const uint32_t b[2]) {
    asm volatile(
        "mma.sync.aligned.m16n8k16.row.col.f32.bf16.bf16.f32 "
        "{%0,%1,%2,%3}, {%4,%5,%6,%7}, {%8,%9}, {%0,%1,%2,%3};\n"
        : "+f"(d[0]), "+f"(d[1]), "+f"(d[2]), "+f"(d[3])
        : "r"(a[0]), "r"(a[1]), "r"(a[2]), "r"(a[3]), "r"(b[0]), "r"(b[1]));
}

// ---------------- weight quantization + bf16 split --------------------------
__global__ void prep_w(const float* __restrict__ w,
                       __nv_bfloat16* __restrict__ oh, __nv_bfloat16* __restrict__ ol,
                       const float* __restrict__ sfp) {
    const int row = blockIdx.x;
    const float* wr = w + (size_t)row * DIM;

    float part = 0.0f;
    for (int c = threadIdx.x; c < DIM; c += blockDim.x) part += fabsf(wr[c]);

    __shared__ float sh[8];
    #pragma unroll
    for (int off = 16; off; off >>= 1)
        part += __shfl_xor_sync(0xffffffffu, part, off);
    if ((threadIdx.x & 31) == 0) sh[threadIdx.x >> 5] = part;
    __syncthreads();
    float tot = 0.0f;
    #pragma unroll
    for (int i = 0; i < 8; i++) tot += sh[i];

    const float scale = fmaxf(tot * (1.0f / (float)DIM), 1e-8f);
    const float thr = 0.7f * scale;
    const float sf = *sfp;
    for (int c = threadIdx.x; c < DIM; c += blockDim.x) {
        float wv = wr[c];
        float wqv = (fabsf(wv) > thr) ? copysignf(scale, wv) : 0.0f;
        float eff = wv + sf * (wqv - wv);
        __nv_bfloat16 h, l;
        split_bf16(eff, h, l);
        oh[(size_t)row * DIM + c] = h;
        ol[(size_t)row * DIM + c] = l;
    }
}

// ---------------- fp32 -> bf16 hi/lo split for activations ------------------
__global__ void split_act(const float* __restrict__ in,
                          __nv_bfloat16* __restrict__ hi, __nv_bfloat16* __restrict__ lo,
                          int n4) {
    int i = blockIdx.x * blockDim.x + threadIdx.x;
    if (i >= n4) return;
    float4 v = ((const float4*)in)[i];
    __nv_bfloat16 h[4], l[4];
    split_bf16(v.x, h[0], l[0]);
    split_bf16(v.y, h[1], l[1]);
    split_bf16(v.z, h[2], l[2]);
    split_bf16(v.w, h[3], l[3]);
    ((uint2*)hi)[i] = *(uint2*)h;
    ((uint2*)lo)[i] = *(uint2*)l;
}

// ---------------- bf16-split tensor-core NT GEMM (ldmatrix + cp.async) ------
#define LDS_K 40
#define GSTG (128 * LDS_K)   // halfs per array per stage

__global__ __launch_bounds__(256, 2)
void gemm_nt_split(const __nv_bfloat16* __restrict__ Ah, const __nv_bfloat16* __restrict__ Al,
                   const __nv_bfloat16* __restrict__ Bh, const __nv_bfloat16* __restrict__ Bl,
                   float* __restrict__ C, int M, int N, int K) {
    extern __shared__ __nv_bfloat16 sm[];
    // stage st: sm + st*4*GSTG; arrays: Ah, Al, Bh, Bl

    const int tid = threadIdx.x;
    const int lane = tid & 31;
    const int wm = (tid >> 5) & 1;
    const int wn = tid >> 6;
    const int m0 = blockIdx.y * 128;
    const int n0 = blockIdx.x * 128;

    float acc[4][4][4];
    #pragma unroll
    for (int i = 0; i < 4; i++)
        #pragma unroll
        for (int j = 0; j < 4; j++)
            #pragma unroll
            for (int r = 0; r < 4; r++) acc[i][j][r] = 0.0f;

    // ldmatrix per-thread source offsets (halfs)
    const int aoff = (wm * 64 + (lane & 15)) * LDS_K + (lane >> 4) * 8;
    const int boff = (wn * 32 + ((lane >> 4) & 1) * 8 + (lane & 7)) * LDS_K
                     + ((lane >> 3) & 1) * 8;

    const int ntiles = K / 32;

    auto load_stage = [&](int st, int k0) {
        __nv_bfloat16* base = sm + st * 4 * GSTG;
        #pragma unroll
        for (int s2 = 0; s2 < 2; s2++) {
            int chunk = tid + s2 * 256;
            int row = chunk >> 2;
            int part = chunk & 3;
            size_t goA = (size_t)(m0 + row) * K + k0 + part * 8;
            size_t goB = (size_t)(n0 + row) * K + k0 + part * 8;
            int so = row * LDS_K + part * 8;
            cp16(base + so, Ah + goA);
            cp16(base + GSTG + so, Al + goA);
            cp16(base + 2 * GSTG + so, Bh + goB);
            cp16(base + 3 * GSTG + so, Bl + goB);
        }
    };

    load_stage(0, 0);
    cp_commit();

    for (int kt = 0; kt < ntiles; kt++) {
        if (kt + 1 < ntiles) {
            load_stage((kt + 1) & 1, (kt + 1) * 32);
            cp_commit();
            cp_wait<1>();
        } else {
            cp_wait<0>();
        }
        __syncthreads();

        const __nv_bfloat16* sAh = sm + (kt & 1) * 4 * GSTG;
        const __nv_bfloat16* sAl = sAh + GSTG;
        const __nv_bfloat16* sBh = sAh + 2 * GSTG;
        const __nv_bfloat16* sBl = sAh + 3 * GSTG;

        #pragma unroll
        for (int ks = 0; ks < 2; ks++) {
            const int ko = ks * 16;
            uint32_t af[4][4], bf_[4][2];

            // pass 1: Ah * Bh
            #pragma unroll
            for (int jp = 0; jp < 2; jp++)
                ldsm_x4(bf_[2 * jp][0], bf_[2 * jp][1], bf_[2 * jp + 1][0],
                        bf_[2 * jp + 1][1], sBh + boff + jp * 16 * LDS_K + ko);
            #pragma unroll
            for (int i = 0; i < 4; i++)
                ldsm_x4(af[i][0], af[i][1], af[i][2], af[i][3],
                        sAh + aoff + i * 16 * LDS_K + ko);
            #pragma unroll
            for (int i = 0; i < 4; i++)
                #pragma unroll
                for (int j = 0; j < 4; j++) mma_bf16(acc[i][j], af[i], bf_[j]);

            // pass 2: Al * Bh (reuse A registers)
            #pragma unroll
            for (int i = 0; i < 4; i++)
                ldsm_x4(af[i][0], af[i][1], af[i][2], af[i][3],
                        sAl + aoff + i * 16 * LDS_K + ko);
            #pragma unroll
            for (int i = 0; i < 4; i++)
                #pragma unroll
                for (int j = 0; j < 4; j++) mma_bf16(acc[i][j], af[i], bf_[j]);

            // pass 3: Ah * Bl (reload Ah, load Bl over Bh regs)
            #pragma unroll
            for (int i = 0; i < 4; i++)
                ldsm_x4(af[i][0], af[i][1], af[i][2], af[i][3],
                        sAh + aoff + i * 16 * LDS_K + ko);
            #pragma unroll
            for (int jp = 0; jp < 2; jp++)
                ldsm_x4(bf_[2 * jp][0], bf_[2 * jp][1], bf_[2 * jp + 1][0],
                        bf_[2 * jp + 1][1], sBl + boff + jp * 16 * LDS_K + ko);
            #pragma unroll
            for (int i = 0; i < 4; i++)
                #pragma unroll
                for (int j = 0; j < 4; j++) mma_bf16(acc[i][j], af[i], bf_[j]);
        }
        __syncthreads();
    }

    const int g = lane >> 2, tig = lane & 3;
    #pragma unroll
    for (int i = 0; i < 4; i++) {
        #pragma unroll
        for (int j = 0; j < 4; j++) {
            int row1 = m0 + wm * 64 + i * 16 + g;
            int col = n0 + wn * 32 + j * 8 + tig * 2;
            float2 lo = make_float2(acc[i][j][0], acc[i][j][1]);
            float2 hi = make_float2(acc[i][j][2], acc[i][j][3]);
            *(float2*)&C[(size_t)row1 * N + col] = lo;
            *(float2*)&C[(size_t)(row1 + 8) * N + col] = hi;
        }
    }
}

// ---------------- fused RMSNorm + RoPE -> bf16 split, head-major layout -----
__global__ void rms_rope_split(const float* __restrict__ in,
                               __nv_bfloat16* __restrict__ oh, __nv_bfloat16* __restrict__ ol,
                               const float* __restrict__ gain, int heads, int T,
                               int in_stride) {
    const int bt = blockIdx.x;
    const int hh = blockIdx.y;
    const int d = threadIdx.x;
    const float* ptr = in + (size_t)bt * in_stride + hh * HD;

    float v = ptr[d];
    float ss = v * v;
    __shared__ float sh[4];
    #pragma unroll
    for (int off = 16; off; off >>= 1)
        ss += __shfl_xor_sync(0xffffffffu, ss, off);
    if ((d & 31) == 0) sh[d >> 5] = ss;
    __syncthreads();
    float tot = sh[0] + sh[1] + sh[2] + sh[3];
    float rs = rsqrtf(tot * (1.0f / (float)HD) + 1.1920928955078125e-07f);

    __shared__ float sn[HD];
    sn[d] = v * rs;
    __syncthreads();

    if (d < HD / 2) {
        const int b = bt / T;
        const int t = bt % T;
        float invf = 1.0f / powf(10000.0f, (float)d * (2.0f / (float)HD));
        float ang = (float)t * invf;
        float c = cosf(ang), s = sinf(ang);
        float x1 = sn[d], x2 = sn[d + HD / 2];
        float gq = gain ? gain[hh] : 1.0f;
        float o1 = (x1 * c + x2 * s) * gq;
        float o2 = (x2 * c - x1 * s) * gq;
        size_t obase = ((size_t)(b * heads + hh) * T + t) * HD;
        __nv_bfloat16 h1, l1, h2, l2;
        split_bf16(o1, h1, l1);
        split_bf16(o2, h2, l2);
        oh[obase + d] = h1;          ol[obase + d] = l1;
        oh[obase + d + HD / 2] = h2; ol[obase + d + HD / 2] = l2;
    }
}

// ---------------- block reduce over 128 threads ------------------------------
__device__ __forceinline__ float blk_sum_128(float val, float* sh) {
    #pragma unroll
    for (int off = 16; off; off >>= 1)
        val += __shfl_xor_sync(0xffffffffu, val, off);
    if ((threadIdx.x & 31) == 0) sh[threadIdx.x >> 5] = val;
    __syncthreads();
    float tot = sh[0] + sh[1] + sh[2] + sh[3];
    __syncthreads();
    return tot;
}

// ---------------- vn = v / max(||v||, 1e-12) ---------------------------------
__global__ void prep_vn(const float* __restrict__ kvbuf, float* __restrict__ vn) {
    __shared__ float sh[4];
    const int bt = blockIdx.x >> 2;
    const int kvh = blockIdx.x & 3;
    const int d = threadIdx.x;
    float v = kvbuf[(size_t)bt * KVW + NKV * HD + kvh * HD + d];
    float ss = blk_sum_128(v * v, sh);
    vn[((size_t)bt * NKV + kvh) * HD + d] = v / fmaxf(sqrtf(ss), 1e-12f);
}

// ---------------- V: split + transpose to [b][kv][d][t] ---------------------
__global__ void split_v_t(const float* __restrict__ kvbuf,
                          __nv_bfloat16* __restrict__ vth, __nv_bfloat16* __restrict__ vtl,
                          int T) {
    __shared__ float tile[32][33];
    const int bkv = blockIdx.z;
    const int b = bkv / NKV, kv = bkv % NKV;
    const int t0 = blockIdx.x * 32, d0 = blockIdx.y * 32;
    const int tx = threadIdx.x, ty = threadIdx.y;

    #pragma unroll
    for (int k = 0; k < 4; k++) {
        int t = t0 + ty + k * 8;
        tile[ty + k * 8][tx] =
            kvbuf[(size_t)(b * T + t) * KVW + NKV * HD + kv * HD + d0 + tx];
    }
    __syncthreads();
    #pragma unroll
    for (int k = 0; k < 4; k++) {
        int d = d0 + ty + k * 8;
        float val = tile[tx][ty + k * 8];
        __nv_bfloat16 h, l;
        split_bf16(val, h, l);
        size_t o = ((size_t)(b * NKV + kv) * HD + d) * T + t0 + tx;
        vth[o] = h;
        vtl[o] = l;
    }
}

// ---------------- causal flash attention + fused vorth + y-split ------------
#define ATT_QS 136
#define ATT_VS 72
#define KV_STG (64 * ATT_QS * 2 + 128 * ATT_VS * 2)

__global__ __launch_bounds__(256, 1)
void attn_mma(const __nv_bfloat16* __restrict__ qh, const __nv_bfloat16* __restrict__ ql,
              const __nv_bfloat16* __restrict__ kh, const __nv_bfloat16* __restrict__ kl,
              const __nv_bfloat16* __restrict__ vth, const __nv_bfloat16* __restrict__ vtl,
              const float* __restrict__ vn,
              __nv_bfloat16* __restrict__ yh, __nv_bfloat16* __restrict__ yl, int T) {
    extern __shared__ __nv_bfloat16 smem_b[];
    __nv_bfloat16* sQh = smem_b;
    __nv_bfloat16* sQl = sQh + 128 * ATT_QS;
    __nv_bfloat16* sKV = sQl + 128 * ATT_QS;

    const int qb = (gridDim.x - 1) - blockIdx.x;
    const int bh = blockIdx.y;
    const int b = bh / NH, h = bh % NH, kv = h / GRP;
    const int tid = threadIdx.x;
    const int w = tid >> 5, lane = tid & 31, g = lane >> 2, tig = lane & 3;

    const size_t kbase0 = (size_t)(b * NKV + kv) * T * HD;
    const size_t vbase0 = (size_t)(b * NKV + kv) * HD * T;

    auto load_kv = [&](int st, int kb) {
        __nv_bfloat16* base = sKV + st * KV_STG;
        __nv_bfloat16* bKh = base;
        __nv_bfloat16* bKl = base + 64 * ATT_QS;
        __nv_bfloat16* bVh = base + 2 * 64 * ATT_QS;
        __nv_bfloat16* bVl = bVh + 128 * ATT_VS;
        const size_t kbase = kbase0 + (size_t)kb * 64 * HD;
        #pragma unroll
        for (int s2 = 0; s2 < 4; s2++) {
            int idx = tid + s2 * 256;
            int r = idx >> 4, dp = (idx & 15) * 8;
            cp16(bKh + r * ATT_QS + dp, kh + kbase + (size_t)r * HD + dp);
            cp16(bKl + r * ATT_QS + dp, kl + kbase + (size_t)r * HD + dp);
        }
        const size_t vbase = vbase0 + (size_t)kb * 64;
        #pragma unroll
        for (int s2 = 0; s2 < 4; s2++) {
            int idx = tid + s2 * 256;
            int d = idx >> 3, kp = (idx & 7) * 8;
            cp16(bVh + d * ATT_VS + kp, vth + vbase + (size_t)d * T + kp);
            cp16(bVl + d * ATT_VS + kp, vtl + vbase + (size_t)d * T + kp);
        }
    };

    const int nkb = 2 * qb + 2;
    load_kv(0, 0);
    cp_commit();

    {
        const size_t qbase = ((size_t)(b * NH + h) * T + qb * 128) * HD;
        for (int idx = tid; idx < 128 * 16; idx += 256) {
            int r = idx >> 4, dp = (idx & 15) * 8;
            *(uint4*)&sQh[r * ATT_QS + dp] = *(const uint4*)&qh[qbase + (size_t)r * HD + dp];
            *(uint4*)&sQl[r * ATT_QS + dp] = *(const uint4*)&ql[qbase + (size_t)r * HD + dp];
        }
    }

    float m_i[2] = {-1e30f, -1e30f};
    float l_i[2] = {0.0f, 0.0f};
    float O[16][4];
    #pragma unroll
    for (int jt = 0; jt < 16; jt++)
        #pragma unroll
        for (int r = 0; r < 4; r++) O[jt][r] = 0.0f;

    const float sc = 0.08838834764831845f;
    const int arow = w * 16;

    const int qoff = (arow + (lane & 15)) * ATT_QS + (lane >> 4) * 8;
    const int koff_f = (((lane >> 4) & 1) * 8 + (lane & 7)) * ATT_QS + ((lane >> 3) & 1) * 8;
    const int voff_f = (((lane >> 4) & 1) * 8 + (lane & 7)) * ATT_VS + ((lane >> 3) & 1) * 8;

    for (int kb = 0; kb < nkb; kb++) {
        if (kb + 1 < nkb) {
            load_kv((kb + 1) & 1, kb + 1);
            cp_commit();
            cp_wait<1>();
        } else {
            cp_wait<0>();
        }
        __syncthreads();

        const __nv_bfloat16* bKh = sKV + (kb & 1) * KV_STG;
        const __nv_bfloat16* bKl = bKh + 64 * ATT_QS;
        const __nv_bfloat16* bVh = bKh + 2 * 64 * ATT_QS;
        const __nv_bfloat16* bVl = bVh + 128 * ATT_VS;

        float s[8][4];
        #pragma unroll
        for (int j = 0; j < 8; j++)
            #pragma unroll
            for (int r = 0; r < 4; r++) s[j][r] = 0.0f;

        #pragma unroll
        for (int kc = 0; kc < 8; kc++) {
            const int ko = kc * 16;
            uint32_t ah[4], al[4];
            ldsm_x4(ah[0], ah[1], ah[2], ah[3], sQh + qoff + ko);
            ldsm_x4(al[0], al[1], al[2], al[3], sQl + qoff + ko);
            #pragma unroll
            for (int jp = 0; jp < 4; jp++) {
                uint32_t kh4[4], kl4[4];
                ldsm_x4(kh4[0], kh4[1], kh4[2], kh4[3],
                        bKh + koff_f + jp * 16 * ATT_QS + ko);
                ldsm_x4(kl4[0], kl4[1], kl4[2], kl4[3],
                        bKl + koff_f + jp * 16 * ATT_QS + ko);
                mma_bf16(s[2 * jp],     ah, &kh4[0]);
                mma_bf16(s[2 * jp],     al, &kh4[0]);
                mma_bf16(s[2 * jp],     ah, &kl4[0]);
                mma_bf16(s[2 * jp + 1], ah, &kh4[2]);
                mma_bf16(s[2 * jp + 1], al, &kh4[2]);
                mma_bf16(s[2 * jp + 1], ah, &kl4[2]);
            }
        }

        const int row0 = qb * 128 + arow + g;
        const bool nomask = (kb * 64 + 63) <= (qb * 128 + arow);
        if (nomask) {
            #pragma unroll
            for (int j = 0; j < 8; j++)
                #pragma unroll
                for (int r = 0; r < 4; r++) s[j][r] *= sc;
        } else {
            #pragma unroll
            for (int j = 0; j < 8; j++) {
                const int c = kb * 64 + j * 8 + tig * 2;
                s[j][0] = (c     <= row0)     ? s[j][0] * sc : -1e30f;
                s[j][1] = (c + 1 <= row0)     ? s[j][1] * sc : -1e30f;
                s[j][2] = (c     <= row0 + 8) ? s[j][2] * sc : -1e30f;
                s[j][3] = (c + 1 <= row0 + 8) ? s[j][3] * sc : -1e30f;
            }
        }

        #pragma unroll
        for (int i = 0; i < 2; i++) {
            float rm = -1e30f;
            #pragma unroll
            for (int j = 0; j < 8; j++)
                rm = fmaxf(rm, fmaxf(s[j][2 * i], s[j][2 * i + 1]));
            rm = fmaxf(rm, __shfl_xor_sync(0xffffffffu, rm, 1));
            rm = fmaxf(rm, __shfl_xor_sync(0xffffffffu, rm, 2));
            const float mnew = fmaxf(m_i[i], rm);
            const float alpha = __expf(m_i[i] - mnew);
            float rs = 0.0f;
            #pragma unroll
            for (int j = 0; j < 8; j++) {
                s[j][2 * i]     = __expf(s[j][2 * i] - mnew);
                s[j][2 * i + 1] = __expf(s[j][2 * i + 1] - mnew);
                rs += s[j][2 * i] + s[j][2 * i + 1];
            }
            rs += __shfl_xor_sync(0xffffffffu, rs, 1);
            rs += __shfl_xor_sync(0xffffffffu, rs, 2);
            l_i[i] = l_i[i] * alpha + rs;
            m_i[i] = mnew;
            #pragma unroll
            for (int jt = 0; jt < 16; jt++) {
                O[jt][2 * i] *= alpha;
                O[jt][2 * i + 1] *= alpha;
            }
        }

        #pragma unroll
        for (int kc = 0; kc < 4; kc++) {
            const int ko = kc * 16;
            uint32_t ph[4], pl[4];
            split2_u32(s[2 * kc][0],     s[2 * kc][1],     ph[0], pl[0]);
            split2_u32(s[2 * kc][2],     s[2 * kc][3],     ph[1], pl[1]);
            split2_u32(s[2 * kc + 1][0], s[2 * kc + 1][1], ph[2], pl[2]);
            split2_u32(s[2 * kc + 1][2], s[2 * kc + 1][3], ph[3], pl[3]);
            #pragma unroll
            for (int jp = 0; jp < 8; jp++) {
                uint32_t vh4[4], vl4[4];
                ldsm_x4(vh4[0], vh4[1], vh4[2], vh4[3],
                        bVh + voff_f + jp * 16 * ATT_VS + ko);
                ldsm_x4(vl4[0], vl4[1], vl4[2], vl4[3],
                        bVl + voff_f + jp * 16 * ATT_VS + ko);
                mma_bf16(O[2 * jp],     ph, &vh4[0]);
                mma_bf16(O[2 * jp],     pl, &vh4[0]);
                mma_bf16(O[2 * jp],     ph, &vl4[0]);
                mma_bf16(O[2 * jp + 1], ph, &vh4[2]);
                mma_bf16(O[2 * jp + 1], pl, &vh4[2]);
                mma_bf16(O[2 * jp + 1], ph, &vl4[2]);
            }
        }
        __syncthreads();
    }

    // ---- fused epilogue: y = y_attn - (y.vn)vn, split to bf16 hi/lo ----
    const float inv0 = 1.0f / l_i[0];
    const float inv1 = 1.0f / l_i[1];
    const int r0 = qb * 128 + arow + g;
    const size_t bt0 = (size_t)b * T + r0;
    const float* vn0p = vn + bt0 * (NKV * HD) + kv * HD;
    const float* vn1p = vn0p + (size_t)8 * (NKV * HD);

    float d0 = 0.0f, d1 = 0.0f;
    #pragma unroll
    for (int jt = 0; jt < 16; jt++) {
        const int col = jt * 8 + tig * 2;
        float2 w0 = *(const float2*)&vn0p[col];
        float2 w1 = *(const float2*)&vn1p[col];
        d0 += O[jt][0] * inv0 * w0.x + O[jt][1] * inv0 * w0.y;
        d1 += O[jt][2] * inv1 * w1.x + O[jt][3] * inv1 * w1.y;
    }
    d0 += __shfl_xor_sync(0xffffffffu, d0, 1);
    d0 += __shfl_xor_sync(0xffffffffu, d0, 2);
    d1 += __shfl_xor_sync(0xffffffffu, d1, 1);
    d1 += __shfl_xor_sync(0xffffffffu, d1, 2);

    #pragma unroll
    for (int jt = 0; jt < 16; jt++) {
        const int col = jt * 8 + tig * 2;
        float2 w0 = *(const float2*)&vn0p[col];
        float2 w1 = *(const float2*)&vn1p[col];
        float o00 = O[jt][0] * inv0 - d0 * w0.x;
        float o01 = O[jt][1] * inv0 - d0 * w0.y;
        float o10 = O[jt][2] * inv1 - d1 * w1.x;
        float o11 = O[jt][3] * inv1 - d1 * w1.y;
        uint32_t hh, ll;
        split2_u32(o00, o01, hh, ll);
        *(uint32_t*)&yh[bt0 * DIM + h * HD + col] = hh;
        *(uint32_t*)&yl[bt0 * DIM + h * HD + col] = ll;
        split2_u32(o10, o11, hh, ll);
        *(uint32_t*)&yh[(bt0 + 8) * DIM + h * HD + col] = hh;
        *(uint32_t*)&yl[(bt0 + 8) * DIM + h * HD + col] = ll;
    }
}

// ---------------- launcher ---------------------------------------------------
extern "C" void kernel_launch(void* const* d_in, const int* in_sizes, int n_in,
                              void* d_out, int out_size) {
    const float* x    = (const float*)d_in[0];
    const float* sfp  = (const float*)d_in[1];
    const float* wq   = (const float*)d_in[2];
    const float* wk   = (const float*)d_in[3];
    const float* wv   = (const float*)d_in[4];
    const float* wp   = (const float*)d_in[5];
    const float* gain = (const float*)d_in[6];

    const int BT = in_sizes[0] / DIM;
    const int T = TSEQ;
    const int Bb = BT / T;

    __nv_bfloat16 *pwqh, *pwql, *pwkvh, *pwkvl, *pwph, *pwpl, *pah, *pal;
    __nv_bfloat16 *pqh, *pql, *pkh, *pkl, *pvth, *pvtl;
    float *pq, *pkv, *pvn;
    cudaGetSymbolAddress((void**)&pwqh, g_wq_h);
    cudaGetSymbolAddress((void**)&pwql, g_wq_l);
    cudaGetSymbolAddress((void**)&pwkvh, g_wkv_h);
    cudaGetSymbolAddress((void**)&pwkvl, g_wkv_l);
    cudaGetSymbolAddress((void**)&pwph, g_wp_h);
    cudaGetSymbolAddress((void**)&pwpl, g_wp_l);
    cudaGetSymbolAddress((void**)&pah, g_a_h);
    cudaGetSymbolAddress((void**)&pal, g_a_l);
    cudaGetSymbolAddress((void**)&pqh, g_qh);
    cudaGetSymbolAddress((void**)&pql, g_ql);
    cudaGetSymbolAddress((void**)&pkh, g_kh);
    cudaGetSymbolAddress((void**)&pkl, g_kl);
    cudaGetSymbolAddress((void**)&pvth, g_vth);
    cudaGetSymbolAddress((void**)&pvtl, g_vtl);
    cudaGetSymbolAddress((void**)&pq, g_q);
    cudaGetSymbolAddress((void**)&pkv, g_kv);
    cudaGetSymbolAddress((void**)&pvn, g_vn);

    // 1) effective weights -> bf16 hi/lo (K and V concatenated)
    prep_w<<<DIM, 256>>>(wq, pwqh, pwql, sfp);
    prep_w<<<NKV * HD, 256>>>(wk, pwkvh, pwkvl, sfp);
    prep_w<<<NKV * HD, 256>>>(wv, pwkvh + (size_t)NKV * HD * DIM,
                              pwkvl + (size_t)NKV * HD * DIM, sfp);
    prep_w<<<DIM, 256>>>(wp, pwph, pwpl, sfp);

    // 2) split x; Q projection + merged KV projection
    const int n4 = BT * DIM / 4;
    const size_t gsmem = (size_t)2 * 4 * GSTG * sizeof(__nv_bfloat16);  // 81920
    cudaFuncSetAttribute(gemm_nt_split, cudaFuncAttributeMaxDynamicSharedMemorySize,
                         (int)gsmem);
    split_act<<<(n4 + 255) / 256, 256>>>(x, pah, pal, n4);
    gemm_nt_split<<<dim3(DIM / 128, BT / 128), 256, gsmem>>>(
        pah, pal, pwqh, pwql, pq, BT, DIM, DIM);
    gemm_nt_split<<<dim3(KVW / 128, BT / 128), 256, gsmem>>>(
        pah, pal, pwkvh, pwkvl, pkv, BT, KVW, DIM);

    // 3) RMS norm + RoPE -> bf16 split; vn; V split+transpose
    rms_rope_split<<<dim3(BT, NH), 128>>>(pq, pqh, pql, gain, NH, T, DIM);
    rms_rope_split<<<dim3(BT, NKV), 128>>>(pkv, pkh, pkl, nullptr, NKV, T, KVW);
    prep_vn<<<BT * NKV, 128>>>(pkv, pvn);
    split_v_t<<<dim3(T / 32, HD / 32, Bb * NKV), dim3(32, 8)>>>(pkv, pvth, pvtl, T);

    // 4) attention + fused vorth + y-split -> g_a_h/g_a_l
    size_t asmem = (size_t)(2 * 128 * ATT_QS + 2 * KV_STG) * sizeof(__nv_bfloat16);
    cudaFuncSetAttribute(attn_mma, cudaFuncAttributeMaxDynamicSharedMemorySize, (int)asmem);
    attn_mma<<<dim3(T / 128, Bb * NH), 256, asmem>>>(
        pqh, pql, pkh, pkl, pvth, pvtl, pvn, pah, pal, T);

    // 5) output projection -> d_out
    gemm_nt_split<<<dim3(DIM / 128, BT / 128), 256, gsmem>>>(
        pah, pal, pwph, pwpl, (float*)d_out, BT, DIM, DIM);
}

// round 8
// speedup vs baseline: 3.3441x; 1.0020x over previous
#include <cuda_runtime.h>
#include <cuda_bf16.h>
#include <cstdint>
#include <math.h>

#define DIM  2048
#define NH   16
#define NKV  4
#define HD   128
#define GRP  (NH / NKV)
#define TSEQ 2048
#define BMAX 2
#define KVW  (2 * NKV * HD)   // 1024: merged K|V projection width

// ---------------- scratch (device globals; no allocation allowed) ----------
__device__ __nv_bfloat16 g_wq_h[DIM * DIM];
__device__ __nv_bfloat16 g_wq_l[DIM * DIM];
__device__ __nv_bfloat16 g_wkv_h[KVW * DIM];
__device__ __nv_bfloat16 g_wkv_l[KVW * DIM];
__device__ __nv_bfloat16 g_wp_h[DIM * DIM];
__device__ __nv_bfloat16 g_wp_l[DIM * DIM];
__device__ __nv_bfloat16 g_a_h[BMAX * TSEQ * DIM];   // activation split (x, then y)
__device__ __nv_bfloat16 g_a_l[BMAX * TSEQ * DIM];
__device__ float g_q[BMAX * TSEQ * DIM];
__device__ float g_kv[BMAX * TSEQ * KVW];            // [bt][K(512)|V(512)]
__device__ float g_vn[BMAX * TSEQ * NKV * HD];       // normalized V
__device__ __nv_bfloat16 g_qh[BMAX * NH * TSEQ * HD];
__device__ __nv_bfloat16 g_ql[BMAX * NH * TSEQ * HD];
__device__ __nv_bfloat16 g_kh[BMAX * NKV * TSEQ * HD];
__device__ __nv_bfloat16 g_kl[BMAX * NKV * TSEQ * HD];
__device__ __nv_bfloat16 g_vth[BMAX * NKV * HD * TSEQ];
__device__ __nv_bfloat16 g_vtl[BMAX * NKV * HD * TSEQ];

__device__ __forceinline__ void split_bf16(float v, __nv_bfloat16& h, __nv_bfloat16& l) {
    h = __float2bfloat16_rn(v);
    l = __float2bfloat16_rn(v - __bfloat162float(h));
}

__device__ __forceinline__ void split2_u32(float x, float y, uint32_t& h, uint32_t& l) {
    __nv_bfloat162 hh = __floats2bfloat162_rn(x, y);
    float rx = x - __bfloat162float(hh.x);
    float ry = y - __bfloat162float(hh.y);
    __nv_bfloat162 ll = __floats2bfloat162_rn(rx, ry);
    h = *(uint32_t*)&hh;
    l = *(uint32_t*)&ll;
}

// ---------------- async copy / ldmatrix / mma.sync helpers ------------------
__device__ __forceinline__ uint32_t smem_u32(const void* p) {
    return (uint32_t)__cvta_generic_to_shared(p);
}
__device__ __forceinline__ void cp16(void* s, const void* g) {
    asm volatile("cp.async.cg.shared.global [%0], [%1], 16;\n"
                 :: "r"(smem_u32(s)), "l"(g));
}
__device__ __forceinline__ void cp_commit() {
    asm volatile("cp.async.commit_group;\n");
}
template <int N>
__device__ __forceinline__ void cp_wait() {
    asm volatile("cp.async.wait_group %0;\n" :: "n"(N));
}
__device__ __forceinline__ void ldsm_x4(uint32_t& r0, uint32_t& r1, uint32_t& r2,
                                        uint32_t& r3, const __nv_bfloat16* p) {
    asm volatile("ldmatrix.sync.aligned.m8n8.x4.shared.b16 {%0,%1,%2,%3}, [%4];\n"
                 : "=r"(r0), "=r"(r1), "=r"(r2), "=r"(r3) : "r"(smem_u32(p)));
}
__device__ __forceinline__ void mma_bf16(float d[4], const uint32_t a[4],
                                         const uint32_t b[2]) {
    asm volatile(
        "mma.sync.aligned.m16n8k16.row.col.f32.bf16.bf16.f32 "
        "{%0,%1,%2,%3}, {%4,%5,%6,%7}, {%8,%9}, {%0,%1,%2,%3};\n"
        : "+f"(d[0]), "+f"(d[1]), "+f"(d[2]), "+f"(d[3])
        : "r"(a[0]), "r"(a[1]), "r"(a[2]), "r"(a[3]), "r"(b[0]), "r"(b[1]));
}

// ---------------- fused weight quantization + bf16 split (all 4 mats) -------
// rows 0..2047 -> wq; 2048..2559 -> wk (kv[0:512]); 2560..3071 -> wv (kv[512:]);
// 3072..5119 -> wp
__global__ void prep_w_all(const float* __restrict__ wq, const float* __restrict__ wk,
                           const float* __restrict__ wv, const float* __restrict__ wp,
                           __nv_bfloat16* __restrict__ qh, __nv_bfloat16* __restrict__ ql,
                           __nv_bfloat16* __restrict__ kvh, __nv_bfloat16* __restrict__ kvl,
                           __nv_bfloat16* __restrict__ ph, __nv_bfloat16* __restrict__ pl,
                           const float* __restrict__ sfp) {
    const int row = blockIdx.x;
    const float* wr;
    __nv_bfloat16 *oh, *ol;
    if (row < 2048) {
        wr = wq + (size_t)row * DIM;
        oh = qh + (size_t)row * DIM;  ol = ql + (size_t)row * DIM;
    } else if (row < 2560) {
        int r = row - 2048;
        wr = wk + (size_t)r * DIM;
        oh = kvh + (size_t)r * DIM;   ol = kvl + (size_t)r * DIM;
    } else if (row < 3072) {
        int r = row - 2560;
        wr = wv + (size_t)r * DIM;
        oh = kvh + (size_t)(r + 512) * DIM;  ol = kvl + (size_t)(r + 512) * DIM;
    } else {
        int r = row - 3072;
        wr = wp + (size_t)r * DIM;
        oh = ph + (size_t)r * DIM;    ol = pl + (size_t)r * DIM;
    }

    float part = 0.0f;
    for (int c = threadIdx.x; c < DIM; c += blockDim.x) part += fabsf(wr[c]);

    __shared__ float sh[8];
    #pragma unroll
    for (int off = 16; off; off >>= 1)
        part += __shfl_xor_sync(0xffffffffu, part, off);
    if ((threadIdx.x & 31) == 0) sh[threadIdx.x >> 5] = part;
    __syncthreads();
    float tot = 0.0f;
    #pragma unroll
    for (int i = 0; i < 8; i++) tot += sh[i];

    const float scale = fmaxf(tot * (1.0f / (float)DIM), 1e-8f);
    const float thr = 0.7f * scale;
    const float sf = *sfp;
    for (int c = threadIdx.x; c < DIM; c += blockDim.x) {
        float wv2 = wr[c];
        float wqv = (fabsf(wv2) > thr) ? copysignf(scale, wv2) : 0.0f;
        float eff = wv2 + sf * (wqv - wv2);
        __nv_bfloat16 h, l;
        split_bf16(eff, h, l);
        oh[c] = h;
        ol[c] = l;
    }
}

// ---------------- fp32 -> bf16 hi/lo split for activations ------------------
__global__ void split_act(const float* __restrict__ in,
                          __nv_bfloat16* __restrict__ hi, __nv_bfloat16* __restrict__ lo,
                          int n4) {
    int i = blockIdx.x * blockDim.x + threadIdx.x;
    if (i >= n4) return;
    float4 v = ((const float4*)in)[i];
    __nv_bfloat16 h[4], l[4];
    split_bf16(v.x, h[0], l[0]);
    split_bf16(v.y, h[1], l[1]);
    split_bf16(v.z, h[2], l[2]);
    split_bf16(v.w, h[3], l[3]);
    ((uint2*)hi)[i] = *(uint2*)h;
    ((uint2*)lo)[i] = *(uint2*)l;
}

// ---------------- bf16-split tensor-core NT GEMM (ldmatrix + cp.async) ------
#define LDS_K 40
#define GSTG (128 * LDS_K)   // halfs per array per stage

__global__ __launch_bounds__(256, 2)
void gemm_nt_split(const __nv_bfloat16* __restrict__ Ah, const __nv_bfloat16* __restrict__ Al,
                   const __nv_bfloat16* __restrict__ Bh, const __nv_bfloat16* __restrict__ Bl,
                   float* __restrict__ C, int M, int N, int K) {
    extern __shared__ __nv_bfloat16 sm[];
    // stage st: sm + st*4*GSTG; arrays: Ah, Al, Bh, Bl

    const int tid = threadIdx.x;
    const int lane = tid & 31;
    const int wm = (tid >> 5) & 1;
    const int wn = tid >> 6;
    const int m0 = blockIdx.y * 128;
    const int n0 = blockIdx.x * 128;

    float acc[4][4][4];
    #pragma unroll
    for (int i = 0; i < 4; i++)
        #pragma unroll
        for (int j = 0; j < 4; j++)
            #pragma unroll
            for (int r = 0; r < 4; r++) acc[i][j][r] = 0.0f;

    // ldmatrix per-thread source offsets (halfs)
    const int aoff = (wm * 64 + (lane & 15)) * LDS_K + (lane >> 4) * 8;
    const int boff = (wn * 32 + ((lane >> 4) & 1) * 8 + (lane & 7)) * LDS_K
                     + ((lane >> 3) & 1) * 8;

    const int ntiles = K / 32;

    auto load_stage = [&](int st, int k0) {
        __nv_bfloat16* base = sm + st * 4 * GSTG;
        #pragma unroll
        for (int s2 = 0; s2 < 2; s2++) {
            int chunk = tid + s2 * 256;
            int row = chunk >> 2;
            int part = chunk & 3;
            size_t goA = (size_t)(m0 + row) * K + k0 + part * 8;
            size_t goB = (size_t)(n0 + row) * K + k0 + part * 8;
            int so = row * LDS_K + part * 8;
            cp16(base + so, Ah + goA);
            cp16(base + GSTG + so, Al + goA);
            cp16(base + 2 * GSTG + so, Bh + goB);
            cp16(base + 3 * GSTG + so, Bl + goB);
        }
    };

    load_stage(0, 0);
    cp_commit();

    for (int kt = 0; kt < ntiles; kt++) {
        if (kt + 1 < ntiles) {
            load_stage((kt + 1) & 1, (kt + 1) * 32);
            cp_commit();
            cp_wait<1>();
        } else {
            cp_wait<0>();
        }
        __syncthreads();

        const __nv_bfloat16* sAh = sm + (kt & 1) * 4 * GSTG;
        const __nv_bfloat16* sAl = sAh + GSTG;
        const __nv_bfloat16* sBh = sAh + 2 * GSTG;
        const __nv_bfloat16* sBl = sAh + 3 * GSTG;

        #pragma unroll
        for (int ks = 0; ks < 2; ks++) {
            const int ko = ks * 16;
            uint32_t af[4][4], bh[4][2], bl[4][2];

            // B fragments resident for the whole k-slice
            #pragma unroll
            for (int jp = 0; jp < 2; jp++) {
                ldsm_x4(bh[2 * jp][0], bh[2 * jp][1], bh[2 * jp + 1][0],
                        bh[2 * jp + 1][1], sBh + boff + jp * 16 * LDS_K + ko);
                ldsm_x4(bl[2 * jp][0], bl[2 * jp][1], bl[2 * jp + 1][0],
                        bl[2 * jp + 1][1], sBl + boff + jp * 16 * LDS_K + ko);
            }

            // pass 1+2: Ah * Bh, Ah * Bl
            #pragma unroll
            for (int i = 0; i < 4; i++)
                ldsm_x4(af[i][0], af[i][1], af[i][2], af[i][3],
                        sAh + aoff + i * 16 * LDS_K + ko);
            #pragma unroll
            for (int i = 0; i < 4; i++)
                #pragma unroll
                for (int j = 0; j < 4; j++) mma_bf16(acc[i][j], af[i], bh[j]);
            #pragma unroll
            for (int i = 0; i < 4; i++)
                #pragma unroll
                for (int j = 0; j < 4; j++) mma_bf16(acc[i][j], af[i], bl[j]);

            // pass 3: Al * Bh (A regs reused)
            #pragma unroll
            for (int i = 0; i < 4; i++)
                ldsm_x4(af[i][0], af[i][1], af[i][2], af[i][3],
                        sAl + aoff + i * 16 * LDS_K + ko);
            #pragma unroll
            for (int i = 0; i < 4; i++)
                #pragma unroll
                for (int j = 0; j < 4; j++) mma_bf16(acc[i][j], af[i], bh[j]);
        }
        __syncthreads();
    }

    const int g = lane >> 2, tig = lane & 3;
    #pragma unroll
    for (int i = 0; i < 4; i++) {
        #pragma unroll
        for (int j = 0; j < 4; j++) {
            int row1 = m0 + wm * 64 + i * 16 + g;
            int col = n0 + wn * 32 + j * 8 + tig * 2;
            float2 lo = make_float2(acc[i][j][0], acc[i][j][1]);
            float2 hi = make_float2(acc[i][j][2], acc[i][j][3]);
            *(float2*)&C[(size_t)row1 * N + col] = lo;
            *(float2*)&C[(size_t)(row1 + 8) * N + col] = hi;
        }
    }
}

// ---------------- fused RMSNorm + RoPE -> bf16 split, head-major layout -----
__global__ void rms_rope_split(const float* __restrict__ in,
                               __nv_bfloat16* __restrict__ oh, __nv_bfloat16* __restrict__ ol,
                               const float* __restrict__ gain, int heads, int T,
                               int in_stride) {
    const int bt = blockIdx.x;
    const int hh = blockIdx.y;
    const int d = threadIdx.x;
    const float* ptr = in + (size_t)bt * in_stride + hh * HD;

    float v = ptr[d];
    float ss = v * v;
    __shared__ float sh[4];
    #pragma unroll
    for (int off = 16; off; off >>= 1)
        ss += __shfl_xor_sync(0xffffffffu, ss, off);
    if ((d & 31) == 0) sh[d >> 5] = ss;
    __syncthreads();
    float tot = sh[0] + sh[1] + sh[2] + sh[3];
    float rs = rsqrtf(tot * (1.0f / (float)HD) + 1.1920928955078125e-07f);

    __shared__ float sn[HD];
    sn[d] = v * rs;
    __syncthreads();

    if (d < HD / 2) {
        const int b = bt / T;
        const int t = bt % T;
        float invf = 1.0f / powf(10000.0f, (float)d * (2.0f / (float)HD));
        float ang = (float)t * invf;
        float c = cosf(ang), s = sinf(ang);
        float x1 = sn[d], x2 = sn[d + HD / 2];
        float gq = gain ? gain[hh] : 1.0f;
        float o1 = (x1 * c + x2 * s) * gq;
        float o2 = (x2 * c - x1 * s) * gq;
        size_t obase = ((size_t)(b * heads + hh) * T + t) * HD;
        __nv_bfloat16 h1, l1, h2, l2;
        split_bf16(o1, h1, l1);
        split_bf16(o2, h2, l2);
        oh[obase + d] = h1;          ol[obase + d] = l1;
        oh[obase + d + HD / 2] = h2; ol[obase + d + HD / 2] = l2;
    }
}

// ---------------- block reduce over 128 threads ------------------------------
__device__ __forceinline__ float blk_sum_128(float val, float* sh) {
    #pragma unroll
    for (int off = 16; off; off >>= 1)
        val += __shfl_xor_sync(0xffffffffu, val, off);
    if ((threadIdx.x & 31) == 0) sh[threadIdx.x >> 5] = val;
    __syncthreads();
    float tot = sh[0] + sh[1] + sh[2] + sh[3];
    __syncthreads();
    return tot;
}

// ---------------- vn = v / max(||v||, 1e-12) ---------------------------------
__global__ void prep_vn(const float* __restrict__ kvbuf, float* __restrict__ vn) {
    __shared__ float sh[4];
    const int bt = blockIdx.x >> 2;
    const int kvh = blockIdx.x & 3;
    const int d = threadIdx.x;
    float v = kvbuf[(size_t)bt * KVW + NKV * HD + kvh * HD + d];
    float ss = blk_sum_128(v * v, sh);
    vn[((size_t)bt * NKV + kvh) * HD + d] = v / fmaxf(sqrtf(ss), 1e-12f);
}

// ---------------- V: split + transpose to [b][kv][d][t] ---------------------
__global__ void split_v_t(const float* __restrict__ kvbuf,
                          __nv_bfloat16* __restrict__ vth, __nv_bfloat16* __restrict__ vtl,
                          int T) {
    __shared__ float tile[32][33];
    const int bkv = blockIdx.z;
    const int b = bkv / NKV, kv = bkv % NKV;
    const int t0 = blockIdx.x * 32, d0 = blockIdx.y * 32;
    const int tx = threadIdx.x, ty = threadIdx.y;

    #pragma unroll
    for (int k = 0; k < 4; k++) {
        int t = t0 + ty + k * 8;
        tile[ty + k * 8][tx] =
            kvbuf[(size_t)(b * T + t) * KVW + NKV * HD + kv * HD + d0 + tx];
    }
    __syncthreads();
    #pragma unroll
    for (int k = 0; k < 4; k++) {
        int d = d0 + ty + k * 8;
        float val = tile[tx][ty + k * 8];
        __nv_bfloat16 h, l;
        split_bf16(val, h, l);
        size_t o = ((size_t)(b * NKV + kv) * HD + d) * T + t0 + tx;
        vth[o] = h;
        vtl[o] = l;
    }
}

// ---------------- causal flash attention + fused vorth + y-split ------------
#define ATT_QS 136
#define ATT_VS 72
#define KV_STG (64 * ATT_QS * 2 + 128 * ATT_VS * 2)

__global__ __launch_bounds__(256, 1)
void attn_mma(const __nv_bfloat16* __restrict__ qh, const __nv_bfloat16* __restrict__ ql,
              const __nv_bfloat16* __restrict__ kh, const __nv_bfloat16* __restrict__ kl,
              const __nv_bfloat16* __restrict__ vth, const __nv_bfloat16* __restrict__ vtl,
              const float* __restrict__ vn,
              __nv_bfloat16* __restrict__ yh, __nv_bfloat16* __restrict__ yl, int T) {
    extern __shared__ __nv_bfloat16 smem_b[];
    __nv_bfloat16* sQh = smem_b;
    __nv_bfloat16* sQl = sQh + 128 * ATT_QS;
    __nv_bfloat16* sKV = sQl + 128 * ATT_QS;

    const int qb = (gridDim.x - 1) - blockIdx.x;
    const int bh2 = blockIdx.y;
    const int b = bh2 / NH, h = bh2 % NH, kv = h / GRP;
    const int tid = threadIdx.x;
    const int w = tid >> 5, lane = tid & 31, g = lane >> 2, tig = lane & 3;

    const size_t kbase0 = (size_t)(b * NKV + kv) * T * HD;
    const size_t vbase0 = (size_t)(b * NKV + kv) * HD * T;

    auto load_kv = [&](int st, int kb) {
        __nv_bfloat16* base = sKV + st * KV_STG;
        __nv_bfloat16* bKh = base;
        __nv_bfloat16* bKl = base + 64 * ATT_QS;
        __nv_bfloat16* bVh = base + 2 * 64 * ATT_QS;
        __nv_bfloat16* bVl = bVh + 128 * ATT_VS;
        const size_t kbase = kbase0 + (size_t)kb * 64 * HD;
        #pragma unroll
        for (int s2 = 0; s2 < 4; s2++) {
            int idx = tid + s2 * 256;
            int r = idx >> 4, dp = (idx & 15) * 8;
            cp16(bKh + r * ATT_QS + dp, kh + kbase + (size_t)r * HD + dp);
            cp16(bKl + r * ATT_QS + dp, kl + kbase + (size_t)r * HD + dp);
        }
        const size_t vbase = vbase0 + (size_t)kb * 64;
        #pragma unroll
        for (int s2 = 0; s2 < 4; s2++) {
            int idx = tid + s2 * 256;
            int d = idx >> 3, kp = (idx & 7) * 8;
            cp16(bVh + d * ATT_VS + kp, vth + vbase + (size_t)d * T + kp);
            cp16(bVl + d * ATT_VS + kp, vtl + vbase + (size_t)d * T + kp);
        }
    };

    const int nkb = 2 * qb + 2;
    load_kv(0, 0);
    cp_commit();

    {
        const size_t qbase = ((size_t)(b * NH + h) * T + qb * 128) * HD;
        for (int idx = tid; idx < 128 * 16; idx += 256) {
            int r = idx >> 4, dp = (idx & 15) * 8;
            *(uint4*)&sQh[r * ATT_QS + dp] = *(const uint4*)&qh[qbase + (size_t)r * HD + dp];
            *(uint4*)&sQl[r * ATT_QS + dp] = *(const uint4*)&ql[qbase + (size_t)r * HD + dp];
        }
    }

    float m_i[2] = {-1e30f, -1e30f};
    float l_i[2] = {0.0f, 0.0f};
    float O[16][4];
    #pragma unroll
    for (int jt = 0; jt < 16; jt++)
        #pragma unroll
        for (int r = 0; r < 4; r++) O[jt][r] = 0.0f;

    const float sc = 0.08838834764831845f;
    const int arow = w * 16;

    const int qoff = (arow + (lane & 15)) * ATT_QS + (lane >> 4) * 8;
    const int koff_f = (((lane >> 4) & 1) * 8 + (lane & 7)) * ATT_QS + ((lane >> 3) & 1) * 8;
    const int voff_f = (((lane >> 4) & 1) * 8 + (lane & 7)) * ATT_VS + ((lane >> 3) & 1) * 8;

    for (int kb = 0; kb < nkb; kb++) {
        if (kb + 1 < nkb) {
            load_kv((kb + 1) & 1, kb + 1);
            cp_commit();
            cp_wait<1>();
        } else {
            cp_wait<0>();
        }
        __syncthreads();

        const __nv_bfloat16* bKh = sKV + (kb & 1) * KV_STG;
        const __nv_bfloat16* bKl = bKh + 64 * ATT_QS;
        const __nv_bfloat16* bVh = bKh + 2 * 64 * ATT_QS;
        const __nv_bfloat16* bVl = bVh + 128 * ATT_VS;

        float s[8][4];
        #pragma unroll
        for (int j = 0; j < 8; j++)
            #pragma unroll
            for (int r = 0; r < 4; r++) s[j][r] = 0.0f;

        #pragma unroll
        for (int kc = 0; kc < 8; kc++) {
            const int ko = kc * 16;
            uint32_t ah[4], al[4];
            ldsm_x4(ah[0], ah[1], ah[2], ah[3], sQh + qoff + ko);
            ldsm_x4(al[0], al[1], al[2], al[3], sQl + qoff + ko);
            #pragma unroll
            for (int jp = 0; jp < 4; jp++) {
                uint32_t kh4[4], kl4[4];
                ldsm_x4(kh4[0], kh4[1], kh4[2], kh4[3],
                        bKh + koff_f + jp * 16 * ATT_QS + ko);
                ldsm_x4(kl4[0], kl4[1], kl4[2], kl4[3],
                        bKl + koff_f + jp * 16 * ATT_QS + ko);
                mma_bf16(s[2 * jp],     ah, &kh4[0]);
                mma_bf16(s[2 * jp],     al, &kh4[0]);
                mma_bf16(s[2 * jp],     ah, &kl4[0]);
                mma_bf16(s[2 * jp + 1], ah, &kh4[2]);
                mma_bf16(s[2 * jp + 1], al, &kh4[2]);
                mma_bf16(s[2 * jp + 1], ah, &kl4[2]);
            }
        }

        const int row0 = qb * 128 + arow + g;
        const bool nomask = (kb * 64 + 63) <= (qb * 128 + arow);
        if (nomask) {
            #pragma unroll
            for (int j = 0; j < 8; j++)
                #pragma unroll
                for (int r = 0; r < 4; r++) s[j][r] *= sc;
        } else {
            #pragma unroll
            for (int j = 0; j < 8; j++) {
                const int c = kb * 64 + j * 8 + tig * 2;
                s[j][0] = (c     <= row0)     ? s[j][0] * sc : -1e30f;
                s[j][1] = (c + 1 <= row0)     ? s[j][1] * sc : -1e30f;
                s[j][2] = (c     <= row0 + 8) ? s[j][2] * sc : -1e30f;
                s[j][3] = (c + 1 <= row0 + 8) ? s[j][3] * sc : -1e30f;
            }
        }

        #pragma unroll
        for (int i = 0; i < 2; i++) {
            float rm = -1e30f;
            #pragma unroll
            for (int j = 0; j < 8; j++)
                rm = fmaxf(rm, fmaxf(s[j][2 * i], s[j][2 * i + 1]));
            rm = fmaxf(rm, __shfl_xor_sync(0xffffffffu, rm, 1));
            rm = fmaxf(rm, __shfl_xor_sync(0xffffffffu, rm, 2));
            const float mnew = fmaxf(m_i[i], rm);
            const float alpha = __expf(m_i[i] - mnew);
            float rs = 0.0f;
            #pragma unroll
            for (int j = 0; j < 8; j++) {
                s[j][2 * i]     = __expf(s[j][2 * i] - mnew);
                s[j][2 * i + 1] = __expf(s[j][2 * i + 1] - mnew);
                rs += s[j][2 * i] + s[j][2 * i + 1];
            }
            rs += __shfl_xor_sync(0xffffffffu, rs, 1);
            rs += __shfl_xor_sync(0xffffffffu, rs, 2);
            l_i[i] = l_i[i] * alpha + rs;
            m_i[i] = mnew;
            #pragma unroll
            for (int jt = 0; jt < 16; jt++) {
                O[jt][2 * i] *= alpha;
                O[jt][2 * i + 1] *= alpha;
            }
        }

        #pragma unroll
        for (int kc = 0; kc < 4; kc++) {
            const int ko = kc * 16;
            uint32_t ph[4], pl[4];
            split2_u32(s[2 * kc][0],     s[2 * kc][1],     ph[0], pl[0]);
            split2_u32(s[2 * kc][2],     s[2 * kc][3],     ph[1], pl[1]);
            split2_u32(s[2 * kc + 1][0], s[2 * kc + 1][1], ph[2], pl[2]);
            split2_u32(s[2 * kc + 1][2], s[2 * kc + 1][3], ph[3], pl[3]);
            #pragma unroll
            for (int jp = 0; jp < 8; jp++) {
                uint32_t vh4[4], vl4[4];
                ldsm_x4(vh4[0], vh4[1], vh4[2], vh4[3],
                        bVh + voff_f + jp * 16 * ATT_VS + ko);
                ldsm_x4(vl4[0], vl4[1], vl4[2], vl4[3],
                        bVl + voff_f + jp * 16 * ATT_VS + ko);
                mma_bf16(O[2 * jp],     ph, &vh4[0]);
                mma_bf16(O[2 * jp],     pl, &vh4[0]);
                mma_bf16(O[2 * jp],     ph, &vl4[0]);
                mma_bf16(O[2 * jp + 1], ph, &vh4[2]);
                mma_bf16(O[2 * jp + 1], pl, &vh4[2]);
                mma_bf16(O[2 * jp + 1], ph, &vl4[2]);
            }
        }
        __syncthreads();
    }

    // ---- fused epilogue: y = y_attn - (y.vn)vn, split to bf16 hi/lo ----
    const float inv0 = 1.0f / l_i[0];
    const float inv1 = 1.0f / l_i[1];
    const int r0 = qb * 128 + arow + g;
    const size_t bt0 = (size_t)b * T + r0;
    const float* vn0p = vn + bt0 * (NKV * HD) + kv * HD;
    const float* vn1p = vn0p + (size_t)8 * (NKV * HD);

    float d0 = 0.0f, d1 = 0.0f;
    #pragma unroll
    for (int jt = 0; jt < 16; jt++) {
        const int col = jt * 8 + tig * 2;
        float2 w0 = *(const float2*)&vn0p[col];
        float2 w1 = *(const float2*)&vn1p[col];
        d0 += O[jt][0] * inv0 * w0.x + O[jt][1] * inv0 * w0.y;
        d1 += O[jt][2] * inv1 * w1.x + O[jt][3] * inv1 * w1.y;
    }
    d0 += __shfl_xor_sync(0xffffffffu, d0, 1);
    d0 += __shfl_xor_sync(0xffffffffu, d0, 2);
    d1 += __shfl_xor_sync(0xffffffffu, d1, 1);
    d1 += __shfl_xor_sync(0xffffffffu, d1, 2);

    #pragma unroll
    for (int jt = 0; jt < 16; jt++) {
        const int col = jt * 8 + tig * 2;
        float2 w0 = *(const float2*)&vn0p[col];
        float2 w1 = *(const float2*)&vn1p[col];
        float o00 = O[jt][0] * inv0 - d0 * w0.x;
        float o01 = O[jt][1] * inv0 - d0 * w0.y;
        float o10 = O[jt][2] * inv1 - d1 * w1.x;
        float o11 = O[jt][3] * inv1 - d1 * w1.y;
        uint32_t hh, ll;
        split2_u32(o00, o01, hh, ll);
        *(uint32_t*)&yh[bt0 * DIM + h * HD + col] = hh;
        *(uint32_t*)&yl[bt0 * DIM + h * HD + col] = ll;
        split2_u32(o10, o11, hh, ll);
        *(uint32_t*)&yh[(bt0 + 8) * DIM + h * HD + col] = hh;
        *(uint32_t*)&yl[(bt0 + 8) * DIM + h * HD + col] = ll;
    }
}

// ---------------- launcher ---------------------------------------------------
extern "C" void kernel_launch(void* const* d_in, const int* in_sizes, int n_in,
                              void* d_out, int out_size) {
    const float* x    = (const float*)d_in[0];
    const float* sfp  = (const float*)d_in[1];
    const float* wq   = (const float*)d_in[2];
    const float* wk   = (const float*)d_in[3];
    const float* wv   = (const float*)d_in[4];
    const float* wp   = (const float*)d_in[5];
    const float* gain = (const float*)d_in[6];

    const int BT = in_sizes[0] / DIM;
    const int T = TSEQ;
    const int Bb = BT / T;

    __nv_bfloat16 *pwqh, *pwql, *pwkvh, *pwkvl, *pwph, *pwpl, *pah, *pal;
    __nv_bfloat16 *pqh, *pql, *pkh, *pkl, *pvth, *pvtl;
    float *pq, *pkv, *pvn;
    cudaGetSymbolAddress((void**)&pwqh, g_wq_h);
    cudaGetSymbolAddress((void**)&pwql, g_wq_l);
    cudaGetSymbolAddress((void**)&pwkvh, g_wkv_h);
    cudaGetSymbolAddress((void**)&pwkvl, g_wkv_l);
    cudaGetSymbolAddress((void**)&pwph, g_wp_h);
    cudaGetSymbolAddress((void**)&pwpl, g_wp_l);
    cudaGetSymbolAddress((void**)&pah, g_a_h);
    cudaGetSymbolAddress((void**)&pal, g_a_l);
    cudaGetSymbolAddress((void**)&pqh, g_qh);
    cudaGetSymbolAddress((void**)&pql, g_ql);
    cudaGetSymbolAddress((void**)&pkh, g_kh);
    cudaGetSymbolAddress((void**)&pkl, g_kl);
    cudaGetSymbolAddress((void**)&pvth, g_vth);
    cudaGetSymbolAddress((void**)&pvtl, g_vtl);
    cudaGetSymbolAddress((void**)&pq, g_q);
    cudaGetSymbolAddress((void**)&pkv, g_kv);
    cudaGetSymbolAddress((void**)&pvn, g_vn);

    // 1) effective weights -> bf16 hi/lo (single fused launch)
    prep_w_all<<<2 * DIM + 2 * NKV * HD, 256>>>(
        wq, wk, wv, wp, pwqh, pwql, pwkvh, pwkvl, pwph, pwpl, sfp);

    // 2) split x; Q projection + merged KV projection
    const int n4 = BT * DIM / 4;
    const size_t gsmem = (size_t)2 * 4 * GSTG * sizeof(__nv_bfloat16);  // 81920
    cudaFuncSetAttribute(gemm_nt_split, cudaFuncAttributeMaxDynamicSharedMemorySize,
                         (int)gsmem);
    split_act<<<(n4 + 255) / 256, 256>>>(x, pah, pal, n4);
    gemm_nt_split<<<dim3(DIM / 128, BT / 128), 256, gsmem>>>(
        pah, pal, pwqh, pwql, pq, BT, DIM, DIM);
    gemm_nt_split<<<dim3(KVW / 128, BT / 128), 256, gsmem>>>(
        pah, pal, pwkvh, pwkvl, pkv, BT, KVW, DIM);

    // 3) RMS norm + RoPE -> bf16 split; vn; V split+transpose
    rms_rope_split<<<dim3(BT, NH), 128>>>(pq, pqh, pql, gain, NH, T, DIM);
    rms_rope_split<<<dim3(BT, NKV), 128>>>(pkv, pkh, pkl, nullptr, NKV, T, KVW);
    prep_vn<<<BT * NKV, 128>>>(pkv, pvn);
    split_v_t<<<dim3(T / 32, HD / 32, Bb * NKV), dim3(32, 8)>>>(pkv, pvth, pvtl, T);

    // 4) attention + fused vorth + y-split -> g_a_h/g_a_l
    size_t asmem = (size_t)(2 * 128 * ATT_QS + 2 * KV_STG) * sizeof(__nv_bfloat16);
    cudaFuncSetAttribute(attn_mma, cudaFuncAttributeMaxDynamicSharedMemorySize, (int)asmem);
    attn_mma<<<dim3(T / 128, Bb * NH), 256, asmem>>>(
        pqh, pql, pkh, pkl, pvth, pvtl, pvn, pah, pal, T);

    // 5) output projection -> d_out
    gemm_nt_split<<<dim3(DIM / 128, BT / 128), 256, gsmem>>>(
        pah, pal, pwph, pwpl, (float*)d_out, BT, DIM, DIM);
}